// round 6
// baseline (speedup 1.0000x reference)
#include <cuda_runtime.h>

typedef unsigned long long u64;
#define FULL 0xffffffffu
#define NQ 10
#define QL 4
#define DM 512
#define NTOK (8*2048)

// Precomputed weight-gate packs per (layer,qubit), row-0 only (W is SU(2)):
// [0]=W00 (re,im), [1]=W01, [2]=S0=iW00+iW01, [3]=D0=iW01-iW00
__device__ u64 g_WP[QL * NQ * 4];

__device__ __forceinline__ u64 pk2(float lo, float hi) {
    u64 r; asm("mov.b64 %0,{%1,%2};" : "=l"(r) : "f"(lo), "f"(hi)); return r;
}
__device__ __forceinline__ void up2(u64 v, float& lo, float& hi) {
    asm("mov.b64 {%0,%1},%2;" : "=f"(lo), "=f"(hi) : "l"(v));
}
__device__ __forceinline__ u64 bc2(float v) { return pk2(v, v); }
__device__ __forceinline__ u64 ffma2(u64 a, u64 b, u64 c) {
    u64 d; asm("fma.rn.f32x2 %0,%1,%2,%3;" : "=l"(d) : "l"(a), "l"(b), "l"(c)); return d;
}
__device__ __forceinline__ u64 fmul2(u64 a, u64 b) {
    u64 d; asm("mul.rn.f32x2 %0,%1,%2;" : "=l"(d) : "l"(a), "l"(b)); return d;
}
__device__ __forceinline__ u64 fadd2(u64 a, u64 b) {
    u64 d; asm("add.rn.f32x2 %0,%1,%2;" : "=l"(d) : "l"(a), "l"(b)); return d;
}
__device__ __forceinline__ u64 swap2(u64 v) { float lo, hi; up2(v, lo, hi); return pk2(hi, lo); }

__global__ void prep_kernel(const float* __restrict__ weights) {
    int t = threadIdx.x;
    if (t < QL * NQ) {
        float ty = 0.5f * weights[t * 2 + 0];
        float tz = 0.5f * weights[t * 2 + 1];
        float sy, cy, sz, cz;
        sincosf(ty, &sy, &cy);
        sincosf(tz, &sz, &cz);
        // W = RZw * RY (SU(2); only row 0 stored)
        float w00r =  cz * cy, w00i = -sz * cy;
        float w01r = -cz * sy, w01i =  sz * sy;
        u64* o = &g_WP[t * 4];
        o[0] = pk2(w00r, w00i);
        o[1] = pk2(w01r, w01i);
        o[2] = pk2(-w00i - w01i, w00r + w01r);   // S0 = iW00 + iW01
        o[3] = pk2( w00i - w01i, w01r - w00r);   // D0 = iW01 - iW00
    }
}

__device__ __forceinline__ float warp_sum(float v) {
#pragma unroll
    for (int o = 16; o; o >>= 1) v += __shfl_xor_sync(FULL, v, o);
    return v;
}

// Fused gate matrix row 0: M = W * (RZt*RX). M is SU(2):
// m11 = conj(m00), m10 = -conj(m01).
__device__ __forceinline__ void build_m2(int l, int q, float c, float s,
    float& m00r, float& m00i, float& m01r, float& m01i)
{
    const u64* w = &g_WP[(l * NQ + q) * 4];
    u64 W00 = w[0], W01 = w[1], S0 = w[2], D0 = w[3];
    float cc = c * c, ss = s * s, sc = s * c;
    u64 M00 = ffma2(bc2(ss), W01, ffma2(bc2(-sc), S0, fmul2(bc2(cc), W00)));
    u64 M01 = ffma2(bc2(-ss), W00, ffma2(bc2(sc), D0, fmul2(bc2(cc), W01)));
    up2(M00, m00r, m00i); up2(M01, m01r, m01i);
}

__global__ void __launch_bounds__(128, 4) qsim_kernel(
    const float* __restrict__ x,
    const float* __restrict__ in_W,
    const float* __restrict__ in_b,
    const float* __restrict__ gamma,
    const float* __restrict__ beta,
    const float* __restrict__ out_W,
    const float* __restrict__ out_b,
    float* __restrict__ out)
{
    const int tid  = threadIdx.x;
    const int lane = tid & 31;
    const int warp = tid >> 5;
    const int token = blockIdx.x * 4 + warp;
    const float* xrow = x + (size_t)token * DM;

    __shared__ float s_cx[NQ][128], s_sx[NQ][128];

    // ---------------- Stage 1: h = tanh(x @ in_W^T + b), LayerNorm ----------
    float acc[NQ];
    {
        float4 xv[4];
#pragma unroll
        for (int i = 0; i < 4; i++)
            xv[i] = *(const float4*)(xrow + lane * 4 + 128 * i);
#pragma unroll
        for (int q = 0; q < NQ; q++) {
            float a = 0.f;
#pragma unroll
            for (int i = 0; i < 4; i++) {
                float4 w = *(const float4*)(in_W + q * DM + lane * 4 + 128 * i);
                a = fmaf(xv[i].x, w.x, a); a = fmaf(xv[i].y, w.y, a);
                a = fmaf(xv[i].z, w.z, a); a = fmaf(xv[i].w, w.w, a);
            }
            acc[q] = warp_sum(a);
        }
    }
    float mu = 0.f;
#pragma unroll
    for (int q = 0; q < NQ; q++) {
        float t = acc[q] + __ldg(&in_b[q]);
        float e = __expf(2.f * t);
        acc[q] = 1.f - __fdividef(2.f, e + 1.f);   // tanh
        mu += acc[q];
    }
    mu *= 0.1f;
    float var = 0.f;
#pragma unroll
    for (int q = 0; q < NQ; q++) { float d = acc[q] - mu; var = fmaf(d, d, var); }
    var *= 0.1f;
    float rstd = rsqrtf(var + 1e-5f);
#pragma unroll
    for (int q = 0; q < NQ; q++) {
        float feat = fmaf((acc[q] - mu) * rstd, __ldg(&gamma[q]), __ldg(&beta[q]));
        float sn, cs;
        __sincosf(0.5f * feat, &sn, &cs);
        s_cx[q][tid] = cs; s_sx[q][tid] = sn;
    }

    // ---------------- Stage 2: 10-qubit statevector sim ---------------------
    // amp index = (vlane << 5) | r, r = 2k + slot, qubit q <-> amp bit (9-q)
    // pr[k]/pi[k] pack amps (r=2k, r=2k+1) re/im as f32x2.
    u64 pr[16], pi[16];

    // --- Layer 0: |0..0> is a product state; build by progressive doubling.
    {
        float m00r, m00i, m01r, m01i;
        // slot level (qubit 9); column0 = (m00, m10) = (m00, -conj(m01))
        build_m2(0, 9, s_cx[9][tid], s_sx[9][tid], m00r, m00i, m01r, m01i);
        pr[0] = pk2(m00r, -m01r);
        pi[0] = pk2(m00i,  m01i);
#pragma unroll
        for (int b = 1; b <= 4; b++) {
            const int qb = 9 - b;
            build_m2(0, qb, s_cx[qb][tid], s_sx[qb][tid], m00r, m00i, m01r, m01i);
            u64 C0r = bc2(m00r), C0i = bc2(m00i), C0in = bc2(-m00i);
            u64 C1r = bc2(-m01r), C1i = bc2(m01i), C1in = bc2(-m01i);
            const int half = 1 << (b - 1);
#pragma unroll
            for (int k = 0; k < 8; k++) {
                if (k >= half) continue;
                u64 fr = pr[k], fi = pi[k];
                pr[k + half] = ffma2(C1in, fi, fmul2(C1r, fr));
                pi[k + half] = ffma2(C1i, fr, fmul2(C1r, fi));
                pr[k] = ffma2(C0in, fi, fmul2(C0r, fr));
                pi[k] = ffma2(C0i, fr, fmul2(C0r, fi));
            }
        }
        // lane factor over qubits 0..4 (lane bit 4-q)
        float lfr = 1.f, lfi = 0.f;
#pragma unroll
        for (int q = 0; q < 5; q++) {
            build_m2(0, q, s_cx[q][tid], s_sx[q][tid], m00r, m00i, m01r, m01i);
            int v = (lane >> (4 - q)) & 1;
            float gr = v ? -m01r : m00r, gi = v ? m01i : m00i;
            float nr = lfr * gr - lfi * gi;
            float ni = lfr * gi + lfi * gr;
            lfr = nr; lfi = ni;
        }
        u64 LFr = bc2(lfr), LFi = bc2(lfi), LFin = bc2(-lfi);
#pragma unroll
        for (int k = 0; k < 16; k++) {
            u64 fr = pr[k], fi = pi[k];
            pr[k] = ffma2(LFin, fi, fmul2(LFr, fr));
            pi[k] = ffma2(LFi, fr, fmul2(LFr, fi));
        }
    }

    // relabel state: vlane = sigma^{-L}(lane); m0..m4 = sigma^L(1<<b)
    int vlane = lane;
    int m0 = 1, m1 = 2, m2 = 4, m3 = 8, m4 = 16;

    // --- gate-phase lambdas (gates within a layer commute: order is free) ---
    auto do_lane = [&](int l) {
        float m00r, m00i, m01r, m01i;
#pragma unroll
        for (int q = 0; q < 5; q++) {
            build_m2(l, q, s_cx[q][tid], s_sx[q][tid], m00r, m00i, m01r, m01i);
            const int lb = 4 - q;
            const int msk = (lb == 4) ? m4 : (lb == 3) ? m3 : (lb == 2) ? m2
                          : (lb == 1) ? m1 : m0;
            int v = (vlane >> lb) & 1;
            // maa = v? conj(m00): m00 ; mab = v? -conj(m01): m01
            float aai = v ? -m00i : m00i;
            float abr = v ? -m01r : m01r;
            u64 AAr = bc2(m00r), AAi = bc2(aai), AAin = bc2(-aai);
            u64 ABr = bc2(abr), ABi = bc2(m01i), ABin = bc2(-m01i);
#pragma unroll
            for (int k = 0; k < 16; k++) {
                float a0, a1, b0, b1;
                up2(pr[k], a0, a1); up2(pi[k], b0, b1);
                float o0 = __shfl_xor_sync(FULL, a0, msk);
                float o1 = __shfl_xor_sync(FULL, a1, msk);
                float p0 = __shfl_xor_sync(FULL, b0, msk);
                float p1 = __shfl_xor_sync(FULL, b1, msk);
                u64 OTR = pk2(o0, o1), OTI = pk2(p0, p1);
                u64 AR = pr[k], AI = pi[k];
                u64 nr = ffma2(ABin, OTI, ffma2(ABr, OTR, ffma2(AAin, AI, fmul2(AAr, AR))));
                u64 ni = ffma2(ABi, OTR, ffma2(ABr, OTI, ffma2(AAi, AR, fmul2(AAr, AI))));
                pr[k] = nr; pi[k] = ni;
            }
        }
    };
    auto do_k = [&](int l) {
        float m00r, m00i, m01r, m01i;
#pragma unroll
        for (int q = 5; q < 9; q++) {
            build_m2(l, q, s_cx[q][tid], s_sx[q][tid], m00r, m00i, m01r, m01i);
            const int tk = 1 << (8 - q);
            // B00=m00 B01=m01 B10=(-m01r,m01i) B11=(m00r,-m00i)
            u64 P00r = bc2(m00r), P00i = bc2(m00i), P00in = bc2(-m00i);
            u64 P01r = bc2(m01r), P01i = bc2(m01i), P01in = bc2(-m01i);
            u64 P01rn = bc2(-m01r);
#pragma unroll
            for (int k = 0; k < 16; k++) {
                if (k & tk) continue;
                const int k2 = k | tk;
                u64 p0r = pr[k], p0i = pi[k], p1r = pr[k2], p1i = pi[k2];
                u64 n0r = ffma2(P01in, p1i, ffma2(P01r, p1r, ffma2(P00in, p0i, fmul2(P00r, p0r))));
                u64 n0i = ffma2(P01i, p1r, ffma2(P01r, p1i, ffma2(P00i, p0r, fmul2(P00r, p0i))));
                u64 n1r = ffma2(P00i, p1i, ffma2(P00r, p1r, ffma2(P01in, p0i, fmul2(P01rn, p0r))));
                u64 n1i = ffma2(P00in, p1r, ffma2(P00r, p1i, ffma2(P01i, p0r, fmul2(P01rn, p0i))));
                pr[k] = n0r; pi[k] = n0i; pr[k2] = n1r; pi[k2] = n1i;
            }
        }
    };
    auto do_slot = [&](int l) {
        float m00r, m00i, m01r, m01i;
        build_m2(l, 9, s_cx[9][tid], s_sx[9][tid], m00r, m00i, m01r, m01i);
        u64 C1 = bc2(m00r), C3 = pk2(m01r, -m01r);
        u64 C2 = pk2(-m00i, m00i), C4 = bc2(-m01i);
        u64 E1 = pk2(m00i, -m00i), E4 = bc2(m01i);
#pragma unroll
        for (int k = 0; k < 16; k++) {
            u64 P = pr[k], Q = pi[k];
            u64 SP = swap2(P), SQ = swap2(Q);
            u64 nr = ffma2(C4, SQ, ffma2(C3, SP, ffma2(C2, Q, fmul2(C1, P))));
            u64 ni = ffma2(E4, SP, ffma2(C3, SQ, ffma2(E1, P, fmul2(C1, Q))));
            pr[k] = nr; pi[k] = ni;
        }
    };

#pragma unroll 1
    for (int l = 0; l < QL; l++) {
        if (l) {
            // Warp-parity staggering: even warps shuffle first, odd warps FMA
            // first, so MIO and FMA pipes overlap across warps on one SMSP.
            if ((warp & 1) == 0) { do_lane(l); do_k(l); do_slot(l); }
            else                 { do_slot(l); do_k(l); do_lane(l); }
        }

        // ---------------- CNOT chain (layers 0..2; layer 3 absorbed) --------
        if (l < 3) {
            // q=0..3 lane perm: SKIPPED -> advance the GF(2) relabeling
            vlane = vlane ^ (vlane >> 1) ^ (vlane >> 2) ^ (vlane >> 3) ^ (vlane >> 4);
            m0 ^= m0 >> 1; m1 ^= m1 >> 1; m2 ^= m2 >> 1; m3 ^= m3 >> 1; m4 ^= m4 >> 1;
            // q=4: control virtual lane bit0, target k bit3
            {
                const bool flip = (vlane & 1);
#pragma unroll
                for (int k = 0; k < 8; k++) {
                    u64 t = pr[k]; pr[k] = flip ? pr[k + 8] : t; pr[k + 8] = flip ? t : pr[k + 8];
                    u64 u = pi[k]; pi[k] = flip ? pi[k + 8] : u; pi[k + 8] = flip ? u : pi[k + 8];
                }
            }
            // q=5..7: pure register swaps (free renames)
#pragma unroll
            for (int q = 5; q < 8; q++) {
                const int ck = 1 << (8 - q), tk2 = 1 << (7 - q);
#pragma unroll
                for (int k = 0; k < 16; k++) {
                    if ((k & ck) && !(k & tk2)) {
                        const int k2 = k | tk2;
                        u64 t = pr[k]; pr[k] = pr[k2]; pr[k2] = t;
                        u64 u = pi[k]; pi[k] = pi[k2]; pi[k2] = u;
                    }
                }
            }
            // q=8: control k bit0, target slot -> swap pack halves for odd k
#pragma unroll
            for (int k = 1; k < 16; k += 2) { pr[k] = swap2(pr[k]); pi[k] = swap2(pi[k]); }
            // q=9: control slot, target virtual lane bit4 -> shuffle hi halves across m4
#pragma unroll
            for (int k = 0; k < 16; k++) {
                float a, b;
                up2(pr[k], a, b); b = __shfl_xor_sync(FULL, b, m4); pr[k] = pk2(a, b);
                up2(pi[k], a, b); b = __shfl_xor_sync(FULL, b, m4); pi[k] = pk2(a, b);
            }
        }
    }

    // ---------------- Stage 3: measurement (final CNOT chain absorbed) ------
    // Final chain is GF(2)-linear on the amp index: post bit B'(q)=9-q maps to
    //   B'=0..8: parity(orig bits B'..9);  B'=9: parity(orig bits 0..8).
    // orig bits: slot = bit0, k = bits1..4, vlane = bits5..9 (virtual!).
    const u64 SGN = 0x8000000080000000ULL;
    u64 AT = 0, A1 = 0, A2 = 0, A3 = 0, A4 = 0;
#pragma unroll
    for (int k = 0; k < 16; k++) {
        u64 P = ffma2(pi[k], pi[k], fmul2(pr[k], pr[k]));
        u64 NP = P ^ SGN;
        const int k3 = (k >> 3) & 1, k2b = (k >> 2) & 1, k1 = (k >> 1) & 1, k0 = k & 1;
        AT = fadd2(AT, P);
        A1 = fadd2(A1, k3 ? NP : P);
        A2 = fadd2(A2, (k3 ^ k2b) ? NP : P);
        A3 = fadd2(A3, (k3 ^ k2b ^ k1) ? NP : P);
        A4 = fadd2(A4, (k3 ^ k2b ^ k1 ^ k0) ? NP : P);
    }
    float lo, hi;
    up2(AT, lo, hi); const float T  = lo + hi;
    up2(A1, lo, hi); const float U1 = lo + hi;
    up2(A2, lo, hi); const float U2 = lo + hi;
    up2(A3, lo, hi); const float U3 = lo + hi;
    up2(A4, lo, hi); const float U4 = lo + hi, Dp = lo - hi;

    const int pl  = __popc(vlane) & 1;
    const int pl4 = __popc(vlane & 15) & 1;
    float z[NQ];
    z[0] = warp_sum(pl4 ? -Dp : Dp);
    z[1] = warp_sum((__popc(vlane >> 3) & 1) ? -T : T);
    z[2] = warp_sum((__popc(vlane >> 2) & 1) ? -T : T);
    z[3] = warp_sum((__popc(vlane >> 1) & 1) ? -T : T);
    z[4] = warp_sum(pl ? -T : T);
    z[5] = warp_sum(pl ? -U1 : U1);
    z[6] = warp_sum(pl ? -U2 : U2);
    z[7] = warp_sum(pl ? -U3 : U3);
    z[8] = warp_sum(pl ? -U4 : U4);
    z[9] = warp_sum(pl ? -Dp : Dp);

    // out = x + q_out @ out_W^T + out_b
    u64 zP[5];
#pragma unroll
    for (int j = 0; j < 5; j++) zP[j] = pk2(z[2 * j], z[2 * j + 1]);

    float* outr = out + (size_t)token * DM;
#pragma unroll
    for (int i = 0; i < 4; i++) {
        const int dbase = lane * 4 + 128 * i;
        float4 xv = *(const float4*)(xrow + dbase);
        float4 ob = *(const float4*)(out_b + dbase);
        float res[4];
#pragma unroll
        for (int c = 0; c < 4; c++) {
            const u64* wrow = (const u64*)(out_W + (dbase + c) * NQ);
            u64 a2 = fmul2(zP[0], wrow[0]);
            a2 = ffma2(zP[1], wrow[1], a2);
            a2 = ffma2(zP[2], wrow[2], a2);
            a2 = ffma2(zP[3], wrow[3], a2);
            a2 = ffma2(zP[4], wrow[4], a2);
            float s0, s1; up2(a2, s0, s1);
            res[c] = s0 + s1;
        }
        float4 o;
        o.x = xv.x + ob.x + res[0];
        o.y = xv.y + ob.y + res[1];
        o.z = xv.z + ob.z + res[2];
        o.w = xv.w + ob.w + res[3];
        *(float4*)(outr + dbase) = o;
    }
}

extern "C" void kernel_launch(void* const* d_in, const int* in_sizes, int n_in,
                              void* d_out, int out_size) {
    const float* x       = (const float*)d_in[0];
    const float* in_W    = (const float*)d_in[1];
    const float* in_b    = (const float*)d_in[2];
    const float* gamma   = (const float*)d_in[3];
    const float* beta    = (const float*)d_in[4];
    const float* weights = (const float*)d_in[5];
    const float* out_W   = (const float*)d_in[6];
    const float* out_b   = (const float*)d_in[7];
    float* out = (float*)d_out;

    prep_kernel<<<1, 64>>>(weights);
    qsim_kernel<<<NTOK / 4, 128>>>(x, in_W, in_b, gamma, beta, out_W, out_b, out);
}

// round 7
// speedup vs baseline: 1.1624x; 1.1624x over previous
#include <cuda_runtime.h>

typedef unsigned long long u64;
#define FULL 0xffffffffu
#define NQ 10
#define QL 4
#define DM 512
#define NTOK (8*2048)

// Precomputed weight-gate packs per (layer,qubit), row-0 only (W is SU(2)):
// [0]=W00 (re,im), [1]=W01, [2]=S0=iW00+iW01, [3]=D0=iW01-iW00
__device__ u64 g_WP[QL * NQ * 4];

__device__ __forceinline__ u64 pk2(float lo, float hi) {
    u64 r; asm("mov.b64 %0,{%1,%2};" : "=l"(r) : "f"(lo), "f"(hi)); return r;
}
__device__ __forceinline__ void up2(u64 v, float& lo, float& hi) {
    asm("mov.b64 {%0,%1},%2;" : "=f"(lo), "=f"(hi) : "l"(v));
}
__device__ __forceinline__ u64 bc2(float v) { return pk2(v, v); }
__device__ __forceinline__ u64 ffma2(u64 a, u64 b, u64 c) {
    u64 d; asm("fma.rn.f32x2 %0,%1,%2,%3;" : "=l"(d) : "l"(a), "l"(b), "l"(c)); return d;
}
__device__ __forceinline__ u64 fmul2(u64 a, u64 b) {
    u64 d; asm("mul.rn.f32x2 %0,%1,%2;" : "=l"(d) : "l"(a), "l"(b)); return d;
}
__device__ __forceinline__ u64 fadd2(u64 a, u64 b) {
    u64 d; asm("add.rn.f32x2 %0,%1,%2;" : "=l"(d) : "l"(a), "l"(b)); return d;
}
__device__ __forceinline__ u64 swap2(u64 v) { float lo, hi; up2(v, lo, hi); return pk2(hi, lo); }

__global__ void prep_kernel(const float* __restrict__ weights) {
    int t = threadIdx.x;
    if (t < QL * NQ) {
        float ty = 0.5f * weights[t * 2 + 0];
        float tz = 0.5f * weights[t * 2 + 1];
        float sy, cy, sz, cz;
        sincosf(ty, &sy, &cy);
        sincosf(tz, &sz, &cz);
        // W = RZw * RY (SU(2); only row 0 stored)
        float w00r =  cz * cy, w00i = -sz * cy;
        float w01r = -cz * sy, w01i =  sz * sy;
        u64* o = &g_WP[t * 4];
        o[0] = pk2(w00r, w00i);
        o[1] = pk2(w01r, w01i);
        o[2] = pk2(-w00i - w01i, w00r + w01r);   // S0 = iW00 + iW01
        o[3] = pk2( w00i - w01i, w01r - w00r);   // D0 = iW01 - iW00
    }
}

__device__ __forceinline__ float warp_sum(float v) {
#pragma unroll
    for (int o = 16; o; o >>= 1) v += __shfl_xor_sync(FULL, v, o);
    return v;
}

// Fused gate matrix row 0: M = W * (RZt*RX). M is SU(2):
// m11 = conj(m00), m10 = -conj(m01).
__device__ __forceinline__ void build_m2(int l, int q, float c, float s,
    float& m00r, float& m00i, float& m01r, float& m01i)
{
    const u64* w = &g_WP[(l * NQ + q) * 4];
    u64 W00 = w[0], W01 = w[1], S0 = w[2], D0 = w[3];
    float cc = c * c, ss = s * s, sc = s * c;
    u64 M00 = ffma2(bc2(ss), W01, ffma2(bc2(-sc), S0, fmul2(bc2(cc), W00)));
    u64 M01 = ffma2(bc2(-ss), W00, ffma2(bc2(sc), D0, fmul2(bc2(cc), W01)));
    up2(M00, m00r, m00i); up2(M01, m01r, m01i);
}

__global__ void __launch_bounds__(128, 5) qsim_kernel(
    const float* __restrict__ x,
    const float* __restrict__ in_W,
    const float* __restrict__ in_b,
    const float* __restrict__ gamma,
    const float* __restrict__ beta,
    const float* __restrict__ out_W,
    const float* __restrict__ out_b,
    float* __restrict__ out)
{
    const int tid  = threadIdx.x;
    const int lane = tid & 31;
    const int warp = tid >> 5;
    const int token = blockIdx.x * 4 + warp;
    const float* xrow = x + (size_t)token * DM;

    __shared__ float s_cx[NQ][128], s_sx[NQ][128];

    // ---------------- Stage 1: h = tanh(x @ in_W^T + b), LayerNorm ----------
    float acc[NQ];
    {
        float4 xv[4];
#pragma unroll
        for (int i = 0; i < 4; i++)
            xv[i] = *(const float4*)(xrow + lane * 4 + 128 * i);
#pragma unroll
        for (int q = 0; q < NQ; q++) {
            float a = 0.f;
#pragma unroll
            for (int i = 0; i < 4; i++) {
                float4 w = *(const float4*)(in_W + q * DM + lane * 4 + 128 * i);
                a = fmaf(xv[i].x, w.x, a); a = fmaf(xv[i].y, w.y, a);
                a = fmaf(xv[i].z, w.z, a); a = fmaf(xv[i].w, w.w, a);
            }
            acc[q] = warp_sum(a);
        }
    }
    float mu = 0.f;
#pragma unroll
    for (int q = 0; q < NQ; q++) {
        float t = acc[q] + __ldg(&in_b[q]);
        float e = __expf(2.f * t);
        acc[q] = 1.f - __fdividef(2.f, e + 1.f);   // tanh
        mu += acc[q];
    }
    mu *= 0.1f;
    float var = 0.f;
#pragma unroll
    for (int q = 0; q < NQ; q++) { float d = acc[q] - mu; var = fmaf(d, d, var); }
    var *= 0.1f;
    float rstd = rsqrtf(var + 1e-5f);
#pragma unroll
    for (int q = 0; q < NQ; q++) {
        float feat = fmaf((acc[q] - mu) * rstd, __ldg(&gamma[q]), __ldg(&beta[q]));
        float sn, cs;
        __sincosf(0.5f * feat, &sn, &cs);
        s_cx[q][tid] = cs; s_sx[q][tid] = sn;
    }

    // ---------------- Stage 2: 10-qubit statevector sim ---------------------
    // amp index = (vlane << 5) | r, r = 2k + slot, qubit q <-> amp bit (9-q)
    // pr[k]/pi[k] pack amps (r=2k, r=2k+1) re/im as f32x2.
    u64 pr[16], pi[16];

    // --- Layer 0: |0..0> is a product state; build by progressive doubling.
    {
        float m00r, m00i, m01r, m01i;
        // slot level (qubit 9); column0 = (m00, m10) = (m00, -conj(m01))
        build_m2(0, 9, s_cx[9][tid], s_sx[9][tid], m00r, m00i, m01r, m01i);
        pr[0] = pk2(m00r, -m01r);
        pi[0] = pk2(m00i,  m01i);
#pragma unroll
        for (int b = 1; b <= 4; b++) {
            const int qb = 9 - b;
            build_m2(0, qb, s_cx[qb][tid], s_sx[qb][tid], m00r, m00i, m01r, m01i);
            u64 C0r = bc2(m00r), C0i = bc2(m00i), C0in = bc2(-m00i);
            u64 C1r = bc2(-m01r), C1i = bc2(m01i), C1in = bc2(-m01i);
            const int half = 1 << (b - 1);
#pragma unroll
            for (int k = 0; k < 8; k++) {
                if (k >= half) continue;
                u64 fr = pr[k], fi = pi[k];
                pr[k + half] = ffma2(C1in, fi, fmul2(C1r, fr));
                pi[k + half] = ffma2(C1i, fr, fmul2(C1r, fi));
                pr[k] = ffma2(C0in, fi, fmul2(C0r, fr));
                pi[k] = ffma2(C0i, fr, fmul2(C0r, fi));
            }
        }
        // lane factor over qubits 0..4 (lane bit 4-q)
        float lfr = 1.f, lfi = 0.f;
#pragma unroll
        for (int q = 0; q < 5; q++) {
            build_m2(0, q, s_cx[q][tid], s_sx[q][tid], m00r, m00i, m01r, m01i);
            int v = (lane >> (4 - q)) & 1;
            float gr = v ? -m01r : m00r, gi = v ? m01i : m00i;
            float nr = lfr * gr - lfi * gi;
            float ni = lfr * gi + lfi * gr;
            lfr = nr; lfi = ni;
        }
        u64 LFr = bc2(lfr), LFi = bc2(lfi), LFin = bc2(-lfi);
#pragma unroll
        for (int k = 0; k < 16; k++) {
            u64 fr = pr[k], fi = pi[k];
            pr[k] = ffma2(LFin, fi, fmul2(LFr, fr));
            pi[k] = ffma2(LFi, fr, fmul2(LFr, fi));
        }
    }

    // relabel state: vlane = sigma^{-L}(lane); m0..m4 = sigma^L(1<<b)
    int vlane = lane;
    int m0 = 1, m1 = 2, m2 = 4, m3 = 8, m4 = 16;

#pragma unroll 1
    for (int l = 0; l < QL; l++) {
        if (l) {
            float m00r, m00i, m01r, m01i;
            // --- lane-bit gates: qubits 0..4, virtual lane bit lb = 4-q ---
#pragma unroll
            for (int q = 0; q < 5; q++) {
                build_m2(l, q, s_cx[q][tid], s_sx[q][tid], m00r, m00i, m01r, m01i);
                const int lb = 4 - q;
                const int msk = (lb == 4) ? m4 : (lb == 3) ? m3 : (lb == 2) ? m2
                              : (lb == 1) ? m1 : m0;
                int v = (vlane >> lb) & 1;
                // maa = v? conj(m00): m00 ; mab = v? -conj(m01): m01
                float aai = v ? -m00i : m00i;
                float abr = v ? -m01r : m01r;
                u64 AAr = bc2(m00r), AAi = bc2(aai), AAin = bc2(-aai);
                u64 ABr = bc2(abr), ABi = bc2(m01i), ABin = bc2(-m01i);
#pragma unroll
                for (int k = 0; k < 16; k++) {
                    float a0, a1, b0, b1;
                    up2(pr[k], a0, a1); up2(pi[k], b0, b1);
                    float o0 = __shfl_xor_sync(FULL, a0, msk);
                    float o1 = __shfl_xor_sync(FULL, a1, msk);
                    float p0 = __shfl_xor_sync(FULL, b0, msk);
                    float p1 = __shfl_xor_sync(FULL, b1, msk);
                    u64 OTR = pk2(o0, o1), OTI = pk2(p0, p1);
                    u64 AR = pr[k], AI = pi[k];
                    u64 nr = ffma2(ABin, OTI, ffma2(ABr, OTR, ffma2(AAin, AI, fmul2(AAr, AR))));
                    u64 ni = ffma2(ABi, OTR, ffma2(ABr, OTI, ffma2(AAi, AR, fmul2(AAr, AI))));
                    pr[k] = nr; pi[k] = ni;
                }
            }
            // --- k-bit gates: qubits 5..8, k bit tk = 1<<(8-q) ---
#pragma unroll
            for (int q = 5; q < 9; q++) {
                build_m2(l, q, s_cx[q][tid], s_sx[q][tid], m00r, m00i, m01r, m01i);
                const int tk = 1 << (8 - q);
                // B00=m00 B01=m01 B10=(-m01r,m01i) B11=(m00r,-m00i)
                u64 P00r = bc2(m00r), P00i = bc2(m00i), P00in = bc2(-m00i);
                u64 P01r = bc2(m01r), P01i = bc2(m01i), P01in = bc2(-m01i);
                u64 P01rn = bc2(-m01r);
#pragma unroll
                for (int k = 0; k < 16; k++) {
                    if (k & tk) continue;
                    const int k2 = k | tk;
                    u64 p0r = pr[k], p0i = pi[k], p1r = pr[k2], p1i = pi[k2];
                    u64 n0r = ffma2(P01in, p1i, ffma2(P01r, p1r, ffma2(P00in, p0i, fmul2(P00r, p0r))));
                    u64 n0i = ffma2(P01i, p1r, ffma2(P01r, p1i, ffma2(P00i, p0r, fmul2(P00r, p0i))));
                    u64 n1r = ffma2(P00i, p1i, ffma2(P00r, p1r, ffma2(P01in, p0i, fmul2(P01rn, p0r))));
                    u64 n1i = ffma2(P00in, p1r, ffma2(P00r, p1i, ffma2(P01i, p0r, fmul2(P01rn, p0i))));
                    pr[k] = n0r; pi[k] = n0i; pr[k2] = n1r; pi[k2] = n1i;
                }
            }
            // --- slot gate: qubit 9 (amp bit 0, within-pack) ---
            {
                build_m2(l, 9, s_cx[9][tid], s_sx[9][tid], m00r, m00i, m01r, m01i);
                u64 C1 = bc2(m00r), C3 = pk2(m01r, -m01r);
                u64 C2 = pk2(-m00i, m00i), C4 = bc2(-m01i);
                u64 E1 = pk2(m00i, -m00i), E4 = bc2(m01i);
#pragma unroll
                for (int k = 0; k < 16; k++) {
                    u64 P = pr[k], Q = pi[k];
                    u64 SP = swap2(P), SQ = swap2(Q);
                    u64 nr = ffma2(C4, SQ, ffma2(C3, SP, ffma2(C2, Q, fmul2(C1, P))));
                    u64 ni = ffma2(E4, SP, ffma2(C3, SQ, ffma2(E1, P, fmul2(C1, Q))));
                    pr[k] = nr; pi[k] = ni;
                }
            }
        }

        // ---------------- CNOT chain (layers 0..2; layer 3 absorbed) --------
        if (l < 3) {
            // q=0..3 lane perm: SKIPPED -> advance the GF(2) relabeling
            vlane = vlane ^ (vlane >> 1) ^ (vlane >> 2) ^ (vlane >> 3) ^ (vlane >> 4);
            m0 ^= m0 >> 1; m1 ^= m1 >> 1; m2 ^= m2 >> 1; m3 ^= m3 >> 1; m4 ^= m4 >> 1;
            // q=4: control virtual lane bit0, target k bit3
            {
                const bool flip = (vlane & 1);
#pragma unroll
                for (int k = 0; k < 8; k++) {
                    u64 t = pr[k]; pr[k] = flip ? pr[k + 8] : t; pr[k + 8] = flip ? t : pr[k + 8];
                    u64 u = pi[k]; pi[k] = flip ? pi[k + 8] : u; pi[k + 8] = flip ? u : pi[k + 8];
                }
            }
            // q=5..7: pure register swaps (free renames)
#pragma unroll
            for (int q = 5; q < 8; q++) {
                const int ck = 1 << (8 - q), tk2 = 1 << (7 - q);
#pragma unroll
                for (int k = 0; k < 16; k++) {
                    if ((k & ck) && !(k & tk2)) {
                        const int k2 = k | tk2;
                        u64 t = pr[k]; pr[k] = pr[k2]; pr[k2] = t;
                        u64 u = pi[k]; pi[k] = pi[k2]; pi[k2] = u;
                    }
                }
            }
            // q=8: control k bit0, target slot -> swap pack halves for odd k
#pragma unroll
            for (int k = 1; k < 16; k += 2) { pr[k] = swap2(pr[k]); pi[k] = swap2(pi[k]); }
            // q=9: control slot, target virtual lane bit4 -> shuffle hi halves across m4
#pragma unroll
            for (int k = 0; k < 16; k++) {
                float a, b;
                up2(pr[k], a, b); b = __shfl_xor_sync(FULL, b, m4); pr[k] = pk2(a, b);
                up2(pi[k], a, b); b = __shfl_xor_sync(FULL, b, m4); pi[k] = pk2(a, b);
            }
        }
    }

    // ---------------- Stage 3: measurement (final CNOT chain absorbed) ------
    // Final chain is GF(2)-linear on the amp index: post bit B'(q)=9-q maps to
    //   B'=0..8: parity(orig bits B'..9);  B'=9: parity(orig bits 0..8).
    // orig bits: slot = bit0, k = bits1..4, vlane = bits5..9 (virtual!).
    const u64 SGN = 0x8000000080000000ULL;
    u64 AT = 0, A1 = 0, A2 = 0, A3 = 0, A4 = 0;
#pragma unroll
    for (int k = 0; k < 16; k++) {
        u64 P = ffma2(pi[k], pi[k], fmul2(pr[k], pr[k]));
        u64 NP = P ^ SGN;
        const int k3 = (k >> 3) & 1, k2b = (k >> 2) & 1, k1 = (k >> 1) & 1, k0 = k & 1;
        AT = fadd2(AT, P);
        A1 = fadd2(A1, k3 ? NP : P);
        A2 = fadd2(A2, (k3 ^ k2b) ? NP : P);
        A3 = fadd2(A3, (k3 ^ k2b ^ k1) ? NP : P);
        A4 = fadd2(A4, (k3 ^ k2b ^ k1 ^ k0) ? NP : P);
    }
    float lo, hi;
    up2(AT, lo, hi); const float T  = lo + hi;
    up2(A1, lo, hi); const float U1 = lo + hi;
    up2(A2, lo, hi); const float U2 = lo + hi;
    up2(A3, lo, hi); const float U3 = lo + hi;
    up2(A4, lo, hi); const float U4 = lo + hi, Dp = lo - hi;

    const int pl  = __popc(vlane) & 1;
    const int pl4 = __popc(vlane & 15) & 1;
    float z[NQ];
    z[0] = warp_sum(pl4 ? -Dp : Dp);
    z[1] = warp_sum((__popc(vlane >> 3) & 1) ? -T : T);
    z[2] = warp_sum((__popc(vlane >> 2) & 1) ? -T : T);
    z[3] = warp_sum((__popc(vlane >> 1) & 1) ? -T : T);
    z[4] = warp_sum(pl ? -T : T);
    z[5] = warp_sum(pl ? -U1 : U1);
    z[6] = warp_sum(pl ? -U2 : U2);
    z[7] = warp_sum(pl ? -U3 : U3);
    z[8] = warp_sum(pl ? -U4 : U4);
    z[9] = warp_sum(pl ? -Dp : Dp);

    // out = x + q_out @ out_W^T + out_b
    u64 zP[5];
#pragma unroll
    for (int j = 0; j < 5; j++) zP[j] = pk2(z[2 * j], z[2 * j + 1]);

    float* outr = out + (size_t)token * DM;
#pragma unroll
    for (int i = 0; i < 4; i++) {
        const int dbase = lane * 4 + 128 * i;
        float4 xv = *(const float4*)(xrow + dbase);
        float4 ob = *(const float4*)(out_b + dbase);
        float res[4];
#pragma unroll
        for (int c = 0; c < 4; c++) {
            const u64* wrow = (const u64*)(out_W + (dbase + c) * NQ);
            u64 a2 = fmul2(zP[0], wrow[0]);
            a2 = ffma2(zP[1], wrow[1], a2);
            a2 = ffma2(zP[2], wrow[2], a2);
            a2 = ffma2(zP[3], wrow[3], a2);
            a2 = ffma2(zP[4], wrow[4], a2);
            float s0, s1; up2(a2, s0, s1);
            res[c] = s0 + s1;
        }
        float4 o;
        o.x = xv.x + ob.x + res[0];
        o.y = xv.y + ob.y + res[1];
        o.z = xv.z + ob.z + res[2];
        o.w = xv.w + ob.w + res[3];
        *(float4*)(outr + dbase) = o;
    }
}

extern "C" void kernel_launch(void* const* d_in, const int* in_sizes, int n_in,
                              void* d_out, int out_size) {
    const float* x       = (const float*)d_in[0];
    const float* in_W    = (const float*)d_in[1];
    const float* in_b    = (const float*)d_in[2];
    const float* gamma   = (const float*)d_in[3];
    const float* beta    = (const float*)d_in[4];
    const float* weights = (const float*)d_in[5];
    const float* out_W   = (const float*)d_in[6];
    const float* out_b   = (const float*)d_in[7];
    float* out = (float*)d_out;

    prep_kernel<<<1, 64>>>(weights);
    qsim_kernel<<<NTOK / 4, 128>>>(x, in_W, in_b, gamma, beta, out_W, out_b, out);
}

// round 9
// speedup vs baseline: 1.2865x; 1.1068x over previous
#include <cuda_runtime.h>

typedef unsigned long long u64;
#define FULL 0xffffffffu
#define NQ 10
#define QL 4
#define DM 512
#define NTOK (8*2048)

// Precomputed weight-gate packs per (layer,qubit), row-0 only (W is SU(2)):
// [0]=W00 (re,im), [1]=W01, [2]=S0=iW00+iW01, [3]=D0=iW01-iW00
__device__ u64 g_WP[QL * NQ * 4];

__device__ __forceinline__ u64 pk2(float lo, float hi) {
    u64 r; asm("mov.b64 %0,{%1,%2};" : "=l"(r) : "f"(lo), "f"(hi)); return r;
}
__device__ __forceinline__ void up2(u64 v, float& lo, float& hi) {
    asm("mov.b64 {%0,%1},%2;" : "=f"(lo), "=f"(hi) : "l"(v));
}
__device__ __forceinline__ u64 bc2(float v) { return pk2(v, v); }
__device__ __forceinline__ u64 ffma2(u64 a, u64 b, u64 c) {
    u64 d; asm("fma.rn.f32x2 %0,%1,%2,%3;" : "=l"(d) : "l"(a), "l"(b), "l"(c)); return d;
}
__device__ __forceinline__ u64 fmul2(u64 a, u64 b) {
    u64 d; asm("mul.rn.f32x2 %0,%1,%2;" : "=l"(d) : "l"(a), "l"(b)); return d;
}
__device__ __forceinline__ u64 fadd2(u64 a, u64 b) {
    u64 d; asm("add.rn.f32x2 %0,%1,%2;" : "=l"(d) : "l"(a), "l"(b)); return d;
}
__device__ __forceinline__ u64 swap2(u64 v) { float lo, hi; up2(v, lo, hi); return pk2(hi, lo); }

__global__ void prep_kernel(const float* __restrict__ weights) {
    int t = threadIdx.x;
    if (t < QL * NQ) {
        float ty = 0.5f * weights[t * 2 + 0];
        float tz = 0.5f * weights[t * 2 + 1];
        float sy, cy, sz, cz;
        sincosf(ty, &sy, &cy);
        sincosf(tz, &sz, &cz);
        // W = RZw * RY (SU(2); only row 0 stored)
        float w00r =  cz * cy, w00i = -sz * cy;
        float w01r = -cz * sy, w01i =  sz * sy;
        u64* o = &g_WP[t * 4];
        o[0] = pk2(w00r, w00i);
        o[1] = pk2(w01r, w01i);
        o[2] = pk2(-w00i - w01i, w00r + w01r);   // S0 = iW00 + iW01
        o[3] = pk2( w00i - w01i, w01r - w00r);   // D0 = iW01 - iW00
    }
}

__device__ __forceinline__ float warp_sum(float v) {
#pragma unroll
    for (int o = 16; o; o >>= 1) v += __shfl_xor_sync(FULL, v, o);
    return v;
}

// Fused gate matrix row 0: M = W * (RZt*RX). M is SU(2):
// m11 = conj(m00), m10 = -conj(m01).
__device__ __forceinline__ void build_m2(int l, int q, float c, float s,
    float& m00r, float& m00i, float& m01r, float& m01i)
{
    const u64* w = &g_WP[(l * NQ + q) * 4];
    u64 W00 = w[0], W01 = w[1], S0 = w[2], D0 = w[3];
    float cc = c * c, ss = s * s, sc = s * c;
    u64 M00 = ffma2(bc2(ss), W01, ffma2(bc2(-sc), S0, fmul2(bc2(cc), W00)));
    u64 M01 = ffma2(bc2(-ss), W00, ffma2(bc2(sc), D0, fmul2(bc2(cc), W01)));
    up2(M00, m00r, m00i); up2(M01, m01r, m01i);
}

__global__ void __launch_bounds__(128, 4) qsim_kernel(
    const float* __restrict__ x,
    const float* __restrict__ in_W,
    const float* __restrict__ in_b,
    const float* __restrict__ gamma,
    const float* __restrict__ beta,
    const float* __restrict__ out_W,
    const float* __restrict__ out_b,
    float* __restrict__ out)
{
    const int tid  = threadIdx.x;
    const int lane = tid & 31;
    const int warp = tid >> 5;
    const int token = blockIdx.x * 4 + warp;
    const float* xrow = x + (size_t)token * DM;

    __shared__ float s_cx[NQ][128], s_sx[NQ][128];

    // ---------------- Stage 1: h = tanh(x @ in_W^T + b), LayerNorm ----------
    float acc[NQ];
    {
        float4 xv[4];
#pragma unroll
        for (int i = 0; i < 4; i++)
            xv[i] = *(const float4*)(xrow + lane * 4 + 128 * i);
#pragma unroll
        for (int q = 0; q < NQ; q++) {
            float a = 0.f;
#pragma unroll
            for (int i = 0; i < 4; i++) {
                float4 w = *(const float4*)(in_W + q * DM + lane * 4 + 128 * i);
                a = fmaf(xv[i].x, w.x, a); a = fmaf(xv[i].y, w.y, a);
                a = fmaf(xv[i].z, w.z, a); a = fmaf(xv[i].w, w.w, a);
            }
            acc[q] = warp_sum(a);
        }
    }
    float mu = 0.f;
#pragma unroll
    for (int q = 0; q < NQ; q++) {
        float t = acc[q] + __ldg(&in_b[q]);
        float e = __expf(2.f * t);
        acc[q] = 1.f - __fdividef(2.f, e + 1.f);   // tanh
        mu += acc[q];
    }
    mu *= 0.1f;
    float var = 0.f;
#pragma unroll
    for (int q = 0; q < NQ; q++) { float d = acc[q] - mu; var = fmaf(d, d, var); }
    var *= 0.1f;
    float rstd = rsqrtf(var + 1e-5f);
#pragma unroll
    for (int q = 0; q < NQ; q++) {
        float feat = fmaf((acc[q] - mu) * rstd, __ldg(&gamma[q]), __ldg(&beta[q]));
        float sn, cs;
        __sincosf(0.5f * feat, &sn, &cs);
        s_cx[q][tid] = cs; s_sx[q][tid] = sn;
    }

    // ---------------- Stage 2: 10-qubit statevector sim ---------------------
    // amp index = (vlane << 5) | r, r = 2k + slot, qubit q <-> amp bit (9-q)
    // pr[k]/pi[k] pack amps (r=2k, r=2k+1) re/im as f32x2.
    u64 pr[16], pi[16];

    // --- Layer 0: |0..0> is a product state; build by progressive doubling.
    {
        float m00r, m00i, m01r, m01i;
        // slot level (qubit 9); column0 = (m00, m10) = (m00, -conj(m01))
        build_m2(0, 9, s_cx[9][tid], s_sx[9][tid], m00r, m00i, m01r, m01i);
        pr[0] = pk2(m00r, -m01r);
        pi[0] = pk2(m00i,  m01i);
#pragma unroll
        for (int b = 1; b <= 4; b++) {
            const int qb = 9 - b;
            build_m2(0, qb, s_cx[qb][tid], s_sx[qb][tid], m00r, m00i, m01r, m01i);
            u64 C0r = bc2(m00r), C0i = bc2(m00i), C0in = bc2(-m00i);
            u64 C1r = bc2(-m01r), C1i = bc2(m01i), C1in = bc2(-m01i);
            const int half = 1 << (b - 1);
#pragma unroll
            for (int k = 0; k < 8; k++) {
                if (k >= half) continue;
                u64 fr = pr[k], fi = pi[k];
                pr[k + half] = ffma2(C1in, fi, fmul2(C1r, fr));
                pi[k + half] = ffma2(C1i, fr, fmul2(C1r, fi));
                pr[k] = ffma2(C0in, fi, fmul2(C0r, fr));
                pi[k] = ffma2(C0i, fr, fmul2(C0r, fi));
            }
        }
        // lane factor over qubits 0..4 (lane bit 4-q)
        float lfr = 1.f, lfi = 0.f;
#pragma unroll
        for (int q = 0; q < 5; q++) {
            build_m2(0, q, s_cx[q][tid], s_sx[q][tid], m00r, m00i, m01r, m01i);
            int v = (lane >> (4 - q)) & 1;
            float gr = v ? -m01r : m00r, gi = v ? m01i : m00i;
            float nr = lfr * gr - lfi * gi;
            float ni = lfr * gi + lfi * gr;
            lfr = nr; lfi = ni;
        }
        u64 LFr = bc2(lfr), LFi = bc2(lfi), LFin = bc2(-lfi);
#pragma unroll
        for (int k = 0; k < 16; k++) {
            u64 fr = pr[k], fi = pi[k];
            pr[k] = ffma2(LFin, fi, fmul2(LFr, fr));
            pi[k] = ffma2(LFi, fr, fmul2(LFr, fi));
        }
    }

    // relabel state: vlane = sigma^{-L}(lane); m0..m4 = sigma^L(1<<b)
    int vlane = lane;
    int m0 = 1, m1 = 2, m2 = 4, m3 = 8, m4 = 16;

#pragma unroll 1
    for (int l = 0; l < QL; l++) {
        if (l) {
            float m00r, m00i, m01r, m01i;
            // --- lane-bit gates: qubits 0..4, virtual lane bit lb = 4-q ---
#pragma unroll
            for (int q = 0; q < 5; q++) {
                build_m2(l, q, s_cx[q][tid], s_sx[q][tid], m00r, m00i, m01r, m01i);
                const int lb = 4 - q;
                const int msk = (lb == 4) ? m4 : (lb == 3) ? m3 : (lb == 2) ? m2
                              : (lb == 1) ? m1 : m0;
                int v = (vlane >> lb) & 1;
                // maa = v? conj(m00): m00 ; mab = v? -conj(m01): m01
                float aai = v ? -m00i : m00i;
                float abr = v ? -m01r : m01r;
                u64 AAr = bc2(m00r), AAi = bc2(aai), AAin = bc2(-aai);
                u64 ABr = bc2(abr), ABi = bc2(m01i), ABin = bc2(-m01i);
#pragma unroll
                for (int k = 0; k < 16; k++) {
                    float a0, a1, b0, b1;
                    up2(pr[k], a0, a1); up2(pi[k], b0, b1);
                    float o0 = __shfl_xor_sync(FULL, a0, msk);
                    float o1 = __shfl_xor_sync(FULL, a1, msk);
                    float p0 = __shfl_xor_sync(FULL, b0, msk);
                    float p1 = __shfl_xor_sync(FULL, b1, msk);
                    u64 OTR = pk2(o0, o1), OTI = pk2(p0, p1);
                    u64 AR = pr[k], AI = pi[k];
                    u64 nr = ffma2(ABin, OTI, ffma2(ABr, OTR, ffma2(AAin, AI, fmul2(AAr, AR))));
                    u64 ni = ffma2(ABi, OTR, ffma2(ABr, OTI, ffma2(AAi, AR, fmul2(AAr, AI))));
                    pr[k] = nr; pi[k] = ni;
                }
            }
            // --- k-bit gates: qubits 5..8, k bit tk = 1<<(8-q) ---
#pragma unroll
            for (int q = 5; q < 9; q++) {
                build_m2(l, q, s_cx[q][tid], s_sx[q][tid], m00r, m00i, m01r, m01i);
                const int tk = 1 << (8 - q);
                // B00=m00 B01=m01 B10=(-m01r,m01i) B11=(m00r,-m00i)
                u64 P00r = bc2(m00r), P00i = bc2(m00i), P00in = bc2(-m00i);
                u64 P01r = bc2(m01r), P01i = bc2(m01i), P01in = bc2(-m01i);
                u64 P01rn = bc2(-m01r);
#pragma unroll
                for (int k = 0; k < 16; k++) {
                    if (k & tk) continue;
                    const int k2 = k | tk;
                    u64 p0r = pr[k], p0i = pi[k], p1r = pr[k2], p1i = pi[k2];
                    u64 n0r = ffma2(P01in, p1i, ffma2(P01r, p1r, ffma2(P00in, p0i, fmul2(P00r, p0r))));
                    u64 n0i = ffma2(P01i, p1r, ffma2(P01r, p1i, ffma2(P00i, p0r, fmul2(P00r, p0i))));
                    u64 n1r = ffma2(P00i, p1i, ffma2(P00r, p1r, ffma2(P01in, p0i, fmul2(P01rn, p0r))));
                    u64 n1i = ffma2(P00in, p1r, ffma2(P00r, p1i, ffma2(P01i, p0r, fmul2(P01rn, p0i))));
                    pr[k] = n0r; pi[k] = n0i; pr[k2] = n1r; pi[k2] = n1i;
                }
            }
            // --- slot gate: qubit 9 (amp bit 0, within-pack) ---
            {
                build_m2(l, 9, s_cx[9][tid], s_sx[9][tid], m00r, m00i, m01r, m01i);
                u64 C1 = bc2(m00r), C3 = pk2(m01r, -m01r);
                u64 C2 = pk2(-m00i, m00i), C4 = bc2(-m01i);
                u64 E1 = pk2(m00i, -m00i), E4 = bc2(m01i);
#pragma unroll
                for (int k = 0; k < 16; k++) {
                    u64 P = pr[k], Q = pi[k];
                    u64 SP = swap2(P), SQ = swap2(Q);
                    u64 nr = ffma2(C4, SQ, ffma2(C3, SP, ffma2(C2, Q, fmul2(C1, P))));
                    u64 ni = ffma2(E4, SP, ffma2(C3, SQ, ffma2(E1, P, fmul2(C1, Q))));
                    pr[k] = nr; pi[k] = ni;
                }
            }
        }

        // ---------------- CNOT chain (layers 0..2; layer 3 absorbed) --------
        if (l < 3) {
            // q=0..3 lane perm: SKIPPED -> advance the GF(2) relabeling
            vlane = vlane ^ (vlane >> 1) ^ (vlane >> 2) ^ (vlane >> 3) ^ (vlane >> 4);
            m0 ^= m0 >> 1; m1 ^= m1 >> 1; m2 ^= m2 >> 1; m3 ^= m3 >> 1; m4 ^= m4 >> 1;
            // q=4: control virtual lane bit0, target k bit3
            {
                const bool flip = (vlane & 1);
#pragma unroll
                for (int k = 0; k < 8; k++) {
                    u64 t = pr[k]; pr[k] = flip ? pr[k + 8] : t; pr[k + 8] = flip ? t : pr[k + 8];
                    u64 u = pi[k]; pi[k] = flip ? pi[k + 8] : u; pi[k + 8] = flip ? u : pi[k + 8];
                }
            }
            // q=5..7: pure register swaps (free renames)
#pragma unroll
            for (int q = 5; q < 8; q++) {
                const int ck = 1 << (8 - q), tk2 = 1 << (7 - q);
#pragma unroll
                for (int k = 0; k < 16; k++) {
                    if ((k & ck) && !(k & tk2)) {
                        const int k2 = k | tk2;
                        u64 t = pr[k]; pr[k] = pr[k2]; pr[k2] = t;
                        u64 u = pi[k]; pi[k] = pi[k2]; pi[k2] = u;
                    }
                }
            }
            // q=8: control k bit0, target slot -> swap pack halves for odd k
#pragma unroll
            for (int k = 1; k < 16; k += 2) { pr[k] = swap2(pr[k]); pi[k] = swap2(pi[k]); }
            // q=9: control slot, target virtual lane bit4 -> shuffle hi halves across m4
#pragma unroll
            for (int k = 0; k < 16; k++) {
                float a, b;
                up2(pr[k], a, b); b = __shfl_xor_sync(FULL, b, m4); pr[k] = pk2(a, b);
                up2(pi[k], a, b); b = __shfl_xor_sync(FULL, b, m4); pi[k] = pk2(a, b);
            }
        }
    }

    // ---------------- Stage 3: measurement (final CNOT chain absorbed) ------
    // Final chain is GF(2)-linear on the amp index: post bit B'(q)=9-q maps to
    //   B'=0..8: parity(orig bits B'..9);  B'=9: parity(orig bits 0..8).
    // orig bits: slot = bit0, k = bits1..4, vlane = bits5..9 (virtual!).
    const u64 SGN = 0x8000000080000000ULL;
    u64 AT = 0, A1 = 0, A2 = 0, A3 = 0, A4 = 0;
#pragma unroll
    for (int k = 0; k < 16; k++) {
        u64 P = ffma2(pi[k], pi[k], fmul2(pr[k], pr[k]));
        u64 NP = P ^ SGN;
        const int k3 = (k >> 3) & 1, k2b = (k >> 2) & 1, k1 = (k >> 1) & 1, k0 = k & 1;
        AT = fadd2(AT, P);
        A1 = fadd2(A1, k3 ? NP : P);
        A2 = fadd2(A2, (k3 ^ k2b) ? NP : P);
        A3 = fadd2(A3, (k3 ^ k2b ^ k1) ? NP : P);
        A4 = fadd2(A4, (k3 ^ k2b ^ k1 ^ k0) ? NP : P);
    }
    float lo, hi;
    up2(AT, lo, hi); const float T  = lo + hi;
    up2(A1, lo, hi); const float U1 = lo + hi;
    up2(A2, lo, hi); const float U2 = lo + hi;
    up2(A3, lo, hi); const float U3 = lo + hi;
    up2(A4, lo, hi); const float U4 = lo + hi, Dp = lo - hi;

    const int pl  = __popc(vlane) & 1;
    const int pl4 = __popc(vlane & 15) & 1;
    float z[NQ];
    z[0] = warp_sum(pl4 ? -Dp : Dp);
    z[1] = warp_sum((__popc(vlane >> 3) & 1) ? -T : T);
    z[2] = warp_sum((__popc(vlane >> 2) & 1) ? -T : T);
    z[3] = warp_sum((__popc(vlane >> 1) & 1) ? -T : T);
    z[4] = warp_sum(pl ? -T : T);
    z[5] = warp_sum(pl ? -U1 : U1);
    z[6] = warp_sum(pl ? -U2 : U2);
    z[7] = warp_sum(pl ? -U3 : U3);
    z[8] = warp_sum(pl ? -U4 : U4);
    z[9] = warp_sum(pl ? -Dp : Dp);

    // out = x + q_out @ out_W^T + out_b
    u64 zP[5];
#pragma unroll
    for (int j = 0; j < 5; j++) zP[j] = pk2(z[2 * j], z[2 * j + 1]);

    float* outr = out + (size_t)token * DM;
#pragma unroll
    for (int i = 0; i < 4; i++) {
        const int dbase = lane * 4 + 128 * i;
        float4 xv = *(const float4*)(xrow + dbase);
        float4 ob = *(const float4*)(out_b + dbase);
        float res[4];
#pragma unroll
        for (int c = 0; c < 4; c++) {
            const u64* wrow = (const u64*)(out_W + (dbase + c) * NQ);
            u64 a2 = fmul2(zP[0], wrow[0]);
            a2 = ffma2(zP[1], wrow[1], a2);
            a2 = ffma2(zP[2], wrow[2], a2);
            a2 = ffma2(zP[3], wrow[3], a2);
            a2 = ffma2(zP[4], wrow[4], a2);
            float s0, s1; up2(a2, s0, s1);
            res[c] = s0 + s1;
        }
        float4 o;
        o.x = xv.x + ob.x + res[0];
        o.y = xv.y + ob.y + res[1];
        o.z = xv.z + ob.z + res[2];
        o.w = xv.w + ob.w + res[3];
        *(float4*)(outr + dbase) = o;
    }
}

extern "C" void kernel_launch(void* const* d_in, const int* in_sizes, int n_in,
                              void* d_out, int out_size) {
    const float* x       = (const float*)d_in[0];
    const float* in_W    = (const float*)d_in[1];
    const float* in_b    = (const float*)d_in[2];
    const float* gamma   = (const float*)d_in[3];
    const float* beta    = (const float*)d_in[4];
    const float* weights = (const float*)d_in[5];
    const float* out_W   = (const float*)d_in[6];
    const float* out_b   = (const float*)d_in[7];
    float* out = (float*)d_out;

    prep_kernel<<<1, 64>>>(weights);
    qsim_kernel<<<NTOK / 4, 128>>>(x, in_W, in_b, gamma, beta, out_W, out_b, out);
}

// round 12
// speedup vs baseline: 1.3290x; 1.0330x over previous
#include <cuda_runtime.h>

typedef unsigned long long u64;
#define FULL 0xffffffffu
#define NQ 10
#define QL 4
#define DM 512
#define NTOK (8*2048)

// Precomputed weight-gate packs per (layer,qubit), row-0 only (W is SU(2)):
// [0]=W00 (re,im), [1]=W01, [2]=S0=iW00+iW01, [3]=D0=iW01-iW00
__device__ u64 g_WP[QL * NQ * 4];

__device__ __forceinline__ u64 pk2(float lo, float hi) {
    u64 r; asm("mov.b64 %0,{%1,%2};" : "=l"(r) : "f"(lo), "f"(hi)); return r;
}
__device__ __forceinline__ void up2(u64 v, float& lo, float& hi) {
    asm("mov.b64 {%0,%1},%2;" : "=f"(lo), "=f"(hi) : "l"(v));
}
__device__ __forceinline__ u64 bc2(float v) { return pk2(v, v); }
__device__ __forceinline__ u64 ffma2(u64 a, u64 b, u64 c) {
    u64 d; asm("fma.rn.f32x2 %0,%1,%2,%3;" : "=l"(d) : "l"(a), "l"(b), "l"(c)); return d;
}
__device__ __forceinline__ u64 fmul2(u64 a, u64 b) {
    u64 d; asm("mul.rn.f32x2 %0,%1,%2;" : "=l"(d) : "l"(a), "l"(b)); return d;
}
__device__ __forceinline__ u64 fadd2(u64 a, u64 b) {
    u64 d; asm("add.rn.f32x2 %0,%1,%2;" : "=l"(d) : "l"(a), "l"(b)); return d;
}
__device__ __forceinline__ u64 swap2(u64 v) { float lo, hi; up2(v, lo, hi); return pk2(hi, lo); }

__global__ void prep_kernel(const float* __restrict__ weights) {
    int t = threadIdx.x;
    if (t < QL * NQ) {
        float ty = 0.5f * weights[t * 2 + 0];
        float tz = 0.5f * weights[t * 2 + 1];
        float sy, cy, sz, cz;
        sincosf(ty, &sy, &cy);
        sincosf(tz, &sz, &cz);
        // W = RZw * RY (SU(2); only row 0 stored)
        float w00r =  cz * cy, w00i = -sz * cy;
        float w01r = -cz * sy, w01i =  sz * sy;
        u64* o = &g_WP[t * 4];
        o[0] = pk2(w00r, w00i);
        o[1] = pk2(w01r, w01i);
        o[2] = pk2(-w00i - w01i, w00r + w01r);   // S0 = iW00 + iW01
        o[3] = pk2( w00i - w01i, w01r - w00r);   // D0 = iW01 - iW00
    }
}

__device__ __forceinline__ float warp_sum(float v) {
#pragma unroll
    for (int o = 16; o; o >>= 1) v += __shfl_xor_sync(FULL, v, o);
    return v;
}

// Fused gate matrix row 0: M = W * (RZt*RX). M is SU(2):
// m11 = conj(m00), m10 = -conj(m01).
__device__ __forceinline__ void build_m2(int l, int q, float c, float s,
    float& m00r, float& m00i, float& m01r, float& m01i)
{
    const u64* w = &g_WP[(l * NQ + q) * 4];
    u64 W00 = w[0], W01 = w[1], S0 = w[2], D0 = w[3];
    float cc = c * c, ss = s * s, sc = s * c;
    u64 M00 = ffma2(bc2(ss), W01, ffma2(bc2(-sc), S0, fmul2(bc2(cc), W00)));
    u64 M01 = ffma2(bc2(-ss), W00, ffma2(bc2(sc), D0, fmul2(bc2(cc), W01)));
    up2(M00, m00r, m00i); up2(M01, m01r, m01i);
}

// Fused pass: one lane-bit gate (SHFL-heavy) interleaved with one independent
// reg-bit gate (pure FMA) at pack granularity. Gates act on distinct qubits,
// hence commute; all lanes run the identical schedule so partner-lane packs
// are always at the same gate-application state when read.
// TK > 0: second gate is the k-bit gate with target bit TK.
// TK == 0: second gate is the slot gate (within-pack).
template <int TK>
__device__ __forceinline__ void fused_pass(
    u64* pr, u64* pi, int msk,
    u64 AAr, u64 AAi, u64 AAin, u64 ABr, u64 ABi, u64 ABin,
    u64 G0, u64 G1, u64 G2, u64 G3, u64 G4, u64 G5, u64 G6)
{
#pragma unroll
    for (int k = 0; k < 16; k++) {
        // --- lane-bit gate on pack k ---
        {
            float a0, a1, b0, b1;
            up2(pr[k], a0, a1); up2(pi[k], b0, b1);
            float o0 = __shfl_xor_sync(FULL, a0, msk);
            float o1 = __shfl_xor_sync(FULL, a1, msk);
            float p0 = __shfl_xor_sync(FULL, b0, msk);
            float p1 = __shfl_xor_sync(FULL, b1, msk);
            u64 OTR = pk2(o0, o1), OTI = pk2(p0, p1);
            u64 AR = pr[k], AI = pi[k];
            pr[k] = ffma2(ABin, OTI, ffma2(ABr, OTR, ffma2(AAin, AI, fmul2(AAr, AR))));
            pi[k] = ffma2(ABi, OTR, ffma2(ABr, OTI, ffma2(AAi, AR, fmul2(AAr, AI))));
        }
        // --- second gate (independent qubit, pure FMA) ---
        if (TK > 0) {
            // k-bit gate: G0..G6 = P00r,P00i,P00in,P01r,P01i,P01in,P01rn
            if (k & TK) {
                const int k0 = k ^ TK;
                u64 p0r = pr[k0], p0i = pi[k0], p1r = pr[k], p1i = pi[k];
                pr[k0] = ffma2(G5, p1i, ffma2(G3, p1r, ffma2(G2, p0i, fmul2(G0, p0r))));
                pi[k0] = ffma2(G4, p1r, ffma2(G3, p1i, ffma2(G1, p0r, fmul2(G0, p0i))));
                pr[k]  = ffma2(G1, p1i, ffma2(G0, p1r, ffma2(G5, p0i, fmul2(G6, p0r))));
                pi[k]  = ffma2(G2, p1r, ffma2(G0, p1i, ffma2(G4, p0r, fmul2(G6, p0i))));
            }
        } else {
            // slot gate: G0..G5 = C1,C2,C3,C4,E1,E4
            u64 P = pr[k], Q = pi[k];
            u64 SP = swap2(P), SQ = swap2(Q);
            pr[k] = ffma2(G3, SQ, ffma2(G2, SP, ffma2(G1, Q, fmul2(G0, P))));
            pi[k] = ffma2(G5, SP, ffma2(G2, SQ, ffma2(G4, P, fmul2(G0, Q))));
        }
    }
}

__global__ void __launch_bounds__(128, 4) qsim_kernel(
    const float* __restrict__ x,
    const float* __restrict__ in_W,
    const float* __restrict__ in_b,
    const float* __restrict__ gamma,
    const float* __restrict__ beta,
    const float* __restrict__ out_W,
    const float* __restrict__ out_b,
    float* __restrict__ out)
{
    const int tid  = threadIdx.x;
    const int lane = tid & 31;
    const int warp = tid >> 5;
    const int token = blockIdx.x * 4 + warp;
    const float* xrow = x + (size_t)token * DM;

    __shared__ float s_cx[NQ][128], s_sx[NQ][128];

    // ---------------- Stage 1: h = tanh(x @ in_W^T + b), LayerNorm ----------
    float acc[NQ];
    {
        float4 xv[4];
#pragma unroll
        for (int i = 0; i < 4; i++)
            xv[i] = *(const float4*)(xrow + lane * 4 + 128 * i);
#pragma unroll
        for (int q = 0; q < NQ; q++) {
            float a = 0.f;
#pragma unroll
            for (int i = 0; i < 4; i++) {
                float4 w = *(const float4*)(in_W + q * DM + lane * 4 + 128 * i);
                a = fmaf(xv[i].x, w.x, a); a = fmaf(xv[i].y, w.y, a);
                a = fmaf(xv[i].z, w.z, a); a = fmaf(xv[i].w, w.w, a);
            }
            acc[q] = warp_sum(a);
        }
    }
    float mu = 0.f;
#pragma unroll
    for (int q = 0; q < NQ; q++) {
        float t = acc[q] + __ldg(&in_b[q]);
        float e = __expf(2.f * t);
        acc[q] = 1.f - __fdividef(2.f, e + 1.f);   // tanh
        mu += acc[q];
    }
    mu *= 0.1f;
    float var = 0.f;
#pragma unroll
    for (int q = 0; q < NQ; q++) { float d = acc[q] - mu; var = fmaf(d, d, var); }
    var *= 0.1f;
    float rstd = rsqrtf(var + 1e-5f);
#pragma unroll
    for (int q = 0; q < NQ; q++) {
        float feat = fmaf((acc[q] - mu) * rstd, __ldg(&gamma[q]), __ldg(&beta[q]));
        float sn, cs;
        __sincosf(0.5f * feat, &sn, &cs);
        s_cx[q][tid] = cs; s_sx[q][tid] = sn;
    }

    // ---------------- Stage 2: 10-qubit statevector sim ---------------------
    // amp index = (vlane << 5) | r, r = 2k + slot, qubit q <-> amp bit (9-q)
    // pr[k]/pi[k] pack amps (r=2k, r=2k+1) re/im as f32x2.
    u64 pr[16], pi[16];

    // --- Layer 0: |0..0> is a product state; build by progressive doubling.
    {
        float m00r, m00i, m01r, m01i;
        // slot level (qubit 9); column0 = (m00, m10) = (m00, -conj(m01))
        build_m2(0, 9, s_cx[9][tid], s_sx[9][tid], m00r, m00i, m01r, m01i);
        pr[0] = pk2(m00r, -m01r);
        pi[0] = pk2(m00i,  m01i);
#pragma unroll
        for (int b = 1; b <= 4; b++) {
            const int qb = 9 - b;
            build_m2(0, qb, s_cx[qb][tid], s_sx[qb][tid], m00r, m00i, m01r, m01i);
            u64 C0r = bc2(m00r), C0i = bc2(m00i), C0in = bc2(-m00i);
            u64 C1r = bc2(-m01r), C1i = bc2(m01i), C1in = bc2(-m01i);
            const int half = 1 << (b - 1);
#pragma unroll
            for (int k = 0; k < 8; k++) {
                if (k >= half) continue;
                u64 fr = pr[k], fi = pi[k];
                pr[k + half] = ffma2(C1in, fi, fmul2(C1r, fr));
                pi[k + half] = ffma2(C1i, fr, fmul2(C1r, fi));
                pr[k] = ffma2(C0in, fi, fmul2(C0r, fr));
                pi[k] = ffma2(C0i, fr, fmul2(C0r, fi));
            }
        }
        // lane factor over qubits 0..4 (lane bit 4-q)
        float lfr = 1.f, lfi = 0.f;
#pragma unroll
        for (int q = 0; q < 5; q++) {
            build_m2(0, q, s_cx[q][tid], s_sx[q][tid], m00r, m00i, m01r, m01i);
            int v = (lane >> (4 - q)) & 1;
            float gr = v ? -m01r : m00r, gi = v ? m01i : m00i;
            float nr = lfr * gr - lfi * gi;
            float ni = lfr * gi + lfi * gr;
            lfr = nr; lfi = ni;
        }
        u64 LFr = bc2(lfr), LFi = bc2(lfi), LFin = bc2(-lfi);
#pragma unroll
        for (int k = 0; k < 16; k++) {
            u64 fr = pr[k], fi = pi[k];
            pr[k] = ffma2(LFin, fi, fmul2(LFr, fr));
            pi[k] = ffma2(LFi, fr, fmul2(LFr, fi));
        }
    }

    // relabel state: vlane = sigma^{-L}(lane); m0..m4 = sigma^L(1<<b)
    int vlane = lane;
    int m0 = 1, m1 = 2, m2 = 4, m3 = 8, m4 = 16;

#pragma unroll 1
    for (int l = 0; l < QL; l++) {
        if (l) {
            float m00r, m00i, m01r, m01i;
            float k00r, k00i, k01r, k01i;
            // 5 fused passes: (lane q0,k q5), (q1,q6), (q2,q7), (q3,q8), (q4,slot q9)
#define LANE_COEFFS(Q, MSKEXPR)                                                \
            build_m2(l, (Q), s_cx[(Q)][tid], s_sx[(Q)][tid],                   \
                     m00r, m00i, m01r, m01i);                                  \
            const int msk_##Q = (MSKEXPR);                                     \
            const int v_##Q = (vlane >> (4 - (Q))) & 1;                        \
            const float aai_##Q = v_##Q ? -m00i : m00i;                        \
            const float abr_##Q = v_##Q ? -m01r : m01r;                        \
            u64 AAr = bc2(m00r), AAi = bc2(aai_##Q), AAin = bc2(-aai_##Q);     \
            u64 ABr = bc2(abr_##Q), ABi = bc2(m01i), ABin = bc2(-m01i);

            { // pass 0: lane q0 (msk m4) + k-gate q5 (tk=8)
                LANE_COEFFS(0, m4)
                build_m2(l, 5, s_cx[5][tid], s_sx[5][tid], k00r, k00i, k01r, k01i);
                fused_pass<8>(pr, pi, msk_0, AAr, AAi, AAin, ABr, ABi, ABin,
                    bc2(k00r), bc2(k00i), bc2(-k00i),
                    bc2(k01r), bc2(k01i), bc2(-k01i), bc2(-k01r));
            }
            { // pass 1: lane q1 (msk m3) + k-gate q6 (tk=4)
                LANE_COEFFS(1, m3)
                build_m2(l, 6, s_cx[6][tid], s_sx[6][tid], k00r, k00i, k01r, k01i);
                fused_pass<4>(pr, pi, msk_1, AAr, AAi, AAin, ABr, ABi, ABin,
                    bc2(k00r), bc2(k00i), bc2(-k00i),
                    bc2(k01r), bc2(k01i), bc2(-k01i), bc2(-k01r));
            }
            { // pass 2: lane q2 (msk m2) + k-gate q7 (tk=2)
                LANE_COEFFS(2, m2)
                build_m2(l, 7, s_cx[7][tid], s_sx[7][tid], k00r, k00i, k01r, k01i);
                fused_pass<2>(pr, pi, msk_2, AAr, AAi, AAin, ABr, ABi, ABin,
                    bc2(k00r), bc2(k00i), bc2(-k00i),
                    bc2(k01r), bc2(k01i), bc2(-k01i), bc2(-k01r));
            }
            { // pass 3: lane q3 (msk m1) + k-gate q8 (tk=1)
                LANE_COEFFS(3, m1)
                build_m2(l, 8, s_cx[8][tid], s_sx[8][tid], k00r, k00i, k01r, k01i);
                fused_pass<1>(pr, pi, msk_3, AAr, AAi, AAin, ABr, ABi, ABin,
                    bc2(k00r), bc2(k00i), bc2(-k00i),
                    bc2(k01r), bc2(k01i), bc2(-k01i), bc2(-k01r));
            }
            { // pass 4: lane q4 (msk m0) + slot gate q9
                LANE_COEFFS(4, m0)
                build_m2(l, 9, s_cx[9][tid], s_sx[9][tid], k00r, k00i, k01r, k01i);
                // C1,C2,C3,C4,E1,E4
                fused_pass<0>(pr, pi, msk_4, AAr, AAi, AAin, ABr, ABi, ABin,
                    bc2(k00r), pk2(-k00i, k00i), pk2(k01r, -k01r),
                    bc2(-k01i), pk2(k00i, -k00i), bc2(k01i), 0);
            }
#undef LANE_COEFFS
        }

        // ---------------- CNOT chain (layers 0..2; layer 3 absorbed) --------
        if (l < 3) {
            // q=0..3 lane perm: SKIPPED -> advance the GF(2) relabeling
            vlane = vlane ^ (vlane >> 1) ^ (vlane >> 2) ^ (vlane >> 3) ^ (vlane >> 4);
            m0 ^= m0 >> 1; m1 ^= m1 >> 1; m2 ^= m2 >> 1; m3 ^= m3 >> 1; m4 ^= m4 >> 1;
            // q=4: control virtual lane bit0, target k bit3
            {
                const bool flip = (vlane & 1);
#pragma unroll
                for (int k = 0; k < 8; k++) {
                    u64 t = pr[k]; pr[k] = flip ? pr[k + 8] : t; pr[k + 8] = flip ? t : pr[k + 8];
                    u64 u = pi[k]; pi[k] = flip ? pi[k + 8] : u; pi[k + 8] = flip ? u : pi[k + 8];
                }
            }
            // q=5..7: pure register swaps (free renames)
#pragma unroll
            for (int q = 5; q < 8; q++) {
                const int ck = 1 << (8 - q), tk2 = 1 << (7 - q);
#pragma unroll
                for (int k = 0; k < 16; k++) {
                    if ((k & ck) && !(k & tk2)) {
                        const int k2 = k | tk2;
                        u64 t = pr[k]; pr[k] = pr[k2]; pr[k2] = t;
                        u64 u = pi[k]; pi[k] = pi[k2]; pi[k2] = u;
                    }
                }
            }
            // q=8: control k bit0, target slot -> swap pack halves for odd k
#pragma unroll
            for (int k = 1; k < 16; k += 2) { pr[k] = swap2(pr[k]); pi[k] = swap2(pi[k]); }
            // q=9: control slot, target virtual lane bit4 -> shuffle hi halves across m4
#pragma unroll
            for (int k = 0; k < 16; k++) {
                float a, b;
                up2(pr[k], a, b); b = __shfl_xor_sync(FULL, b, m4); pr[k] = pk2(a, b);
                up2(pi[k], a, b); b = __shfl_xor_sync(FULL, b, m4); pi[k] = pk2(a, b);
            }
        }
    }

    // ---------------- Stage 3: measurement (final CNOT chain absorbed) ------
    // Final chain is GF(2)-linear on the amp index: post bit B'(q)=9-q maps to
    //   B'=0..8: parity(orig bits B'..9);  B'=9: parity(orig bits 0..8).
    // orig bits: slot = bit0, k = bits1..4, vlane = bits5..9 (virtual!).
    const u64 SGN = 0x8000000080000000ULL;
    u64 AT = 0, A1 = 0, A2 = 0, A3 = 0, A4 = 0;
#pragma unroll
    for (int k = 0; k < 16; k++) {
        u64 P = ffma2(pi[k], pi[k], fmul2(pr[k], pr[k]));
        u64 NP = P ^ SGN;
        const int k3 = (k >> 3) & 1, k2b = (k >> 2) & 1, k1 = (k >> 1) & 1, k0 = k & 1;
        AT = fadd2(AT, P);
        A1 = fadd2(A1, k3 ? NP : P);
        A2 = fadd2(A2, (k3 ^ k2b) ? NP : P);
        A3 = fadd2(A3, (k3 ^ k2b ^ k1) ? NP : P);
        A4 = fadd2(A4, (k3 ^ k2b ^ k1 ^ k0) ? NP : P);
    }
    float lo, hi;
    up2(AT, lo, hi); const float T  = lo + hi;
    up2(A1, lo, hi); const float U1 = lo + hi;
    up2(A2, lo, hi); const float U2 = lo + hi;
    up2(A3, lo, hi); const float U3 = lo + hi;
    up2(A4, lo, hi); const float U4 = lo + hi, Dp = lo - hi;

    const int pl  = __popc(vlane) & 1;
    const int pl4 = __popc(vlane & 15) & 1;
    float z[NQ];
    z[0] = warp_sum(pl4 ? -Dp : Dp);
    z[1] = warp_sum((__popc(vlane >> 3) & 1) ? -T : T);
    z[2] = warp_sum((__popc(vlane >> 2) & 1) ? -T : T);
    z[3] = warp_sum((__popc(vlane >> 1) & 1) ? -T : T);
    z[4] = warp_sum(pl ? -T : T);
    z[5] = warp_sum(pl ? -U1 : U1);
    z[6] = warp_sum(pl ? -U2 : U2);
    z[7] = warp_sum(pl ? -U3 : U3);
    z[8] = warp_sum(pl ? -U4 : U4);
    z[9] = warp_sum(pl ? -Dp : Dp);

    // out = x + q_out @ out_W^T + out_b
    u64 zP[5];
#pragma unroll
    for (int j = 0; j < 5; j++) zP[j] = pk2(z[2 * j], z[2 * j + 1]);

    float* outr = out + (size_t)token * DM;
#pragma unroll
    for (int i = 0; i < 4; i++) {
        const int dbase = lane * 4 + 128 * i;
        float4 xv = *(const float4*)(xrow + dbase);
        float4 ob = *(const float4*)(out_b + dbase);
        float res[4];
#pragma unroll
        for (int c = 0; c < 4; c++) {
            const u64* wrow = (const u64*)(out_W + (dbase + c) * NQ);
            u64 a2 = fmul2(zP[0], wrow[0]);
            a2 = ffma2(zP[1], wrow[1], a2);
            a2 = ffma2(zP[2], wrow[2], a2);
            a2 = ffma2(zP[3], wrow[3], a2);
            a2 = ffma2(zP[4], wrow[4], a2);
            float s0, s1; up2(a2, s0, s1);
            res[c] = s0 + s1;
        }
        float4 o;
        o.x = xv.x + ob.x + res[0];
        o.y = xv.y + ob.y + res[1];
        o.z = xv.z + ob.z + res[2];
        o.w = xv.w + ob.w + res[3];
        *(float4*)(outr + dbase) = o;
    }
}

extern "C" void kernel_launch(void* const* d_in, const int* in_sizes, int n_in,
                              void* d_out, int out_size) {
    const float* x       = (const float*)d_in[0];
    const float* in_W    = (const float*)d_in[1];
    const float* in_b    = (const float*)d_in[2];
    const float* gamma   = (const float*)d_in[3];
    const float* beta    = (const float*)d_in[4];
    const float* weights = (const float*)d_in[5];
    const float* out_W   = (const float*)d_in[6];
    const float* out_b   = (const float*)d_in[7];
    float* out = (float*)d_out;

    prep_kernel<<<1, 64>>>(weights);
    qsim_kernel<<<NTOK / 4, 128>>>(x, in_W, in_b, gamma, beta, out_W, out_b, out);
}

// round 13
// speedup vs baseline: 1.4545x; 1.0944x over previous
#include <cuda_runtime.h>

typedef unsigned long long u64;
#define FULL 0xffffffffu
#define NQ 10
#define QL 4
#define DM 512
#define NTOK (8*2048)

// Precomputed weight-gate packs per (layer,qubit), row-0 only (W is SU(2)):
// [0]=W00 (re,im), [1]=W01, [2]=S0=iW00+iW01, [3]=D0=iW01-iW00
__device__ u64 g_WP[QL * NQ * 4];
// Transposed output projection: g_WT[q][j] = (out_W[2j][q], out_W[2j+1][q])
__device__ __align__(16) u64 g_WT[NQ][DM / 2];

__device__ __forceinline__ u64 pk2(float lo, float hi) {
    u64 r; asm("mov.b64 %0,{%1,%2};" : "=l"(r) : "f"(lo), "f"(hi)); return r;
}
__device__ __forceinline__ void up2(u64 v, float& lo, float& hi) {
    asm("mov.b64 {%0,%1},%2;" : "=f"(lo), "=f"(hi) : "l"(v));
}
__device__ __forceinline__ u64 bc2(float v) { return pk2(v, v); }
__device__ __forceinline__ u64 ffma2(u64 a, u64 b, u64 c) {
    u64 d; asm("fma.rn.f32x2 %0,%1,%2,%3;" : "=l"(d) : "l"(a), "l"(b), "l"(c)); return d;
}
__device__ __forceinline__ u64 fmul2(u64 a, u64 b) {
    u64 d; asm("mul.rn.f32x2 %0,%1,%2;" : "=l"(d) : "l"(a), "l"(b)); return d;
}
__device__ __forceinline__ u64 fadd2(u64 a, u64 b) {
    u64 d; asm("add.rn.f32x2 %0,%1,%2;" : "=l"(d) : "l"(a), "l"(b)); return d;
}
__device__ __forceinline__ u64 swap2(u64 v) { float lo, hi; up2(v, lo, hi); return pk2(hi, lo); }

__global__ void prep_kernel(const float* __restrict__ weights,
                            const float* __restrict__ out_W) {
    int t = threadIdx.x;
    if (t < QL * NQ) {
        float ty = 0.5f * weights[t * 2 + 0];
        float tz = 0.5f * weights[t * 2 + 1];
        float sy, cy, sz, cz;
        sincosf(ty, &sy, &cy);
        sincosf(tz, &sz, &cz);
        // W = RZw * RY (SU(2); only row 0 stored)
        float w00r =  cz * cy, w00i = -sz * cy;
        float w01r = -cz * sy, w01i =  sz * sy;
        u64* o = &g_WP[t * 4];
        o[0] = pk2(w00r, w00i);
        o[1] = pk2(w01r, w01i);
        o[2] = pk2(-w00i - w01i, w00r + w01r);   // S0 = iW00 + iW01
        o[3] = pk2( w00i - w01i, w01r - w00r);   // D0 = iW01 - iW00
    }
    // Transpose out_W [DM][NQ] -> g_WT [NQ][DM/2] (f32x2 pairs along d)
    for (int idx = t; idx < NQ * (DM / 2); idx += 256) {
        int q = idx >> 8;          // DM/2 == 256
        int j = idx & 255;
        g_WT[q][j] = pk2(out_W[(2 * j) * NQ + q], out_W[(2 * j + 1) * NQ + q]);
    }
}

__device__ __forceinline__ float warp_sum(float v) {
#pragma unroll
    for (int o = 16; o; o >>= 1) v += __shfl_xor_sync(FULL, v, o);
    return v;
}

// Fused gate matrix row 0: M = W * (RZt*RX). M is SU(2):
// m11 = conj(m00), m10 = -conj(m01).
__device__ __forceinline__ void build_m2(int l, int q, float c, float s,
    float& m00r, float& m00i, float& m01r, float& m01i)
{
    const u64* w = &g_WP[(l * NQ + q) * 4];
    u64 W00 = w[0], W01 = w[1], S0 = w[2], D0 = w[3];
    float cc = c * c, ss = s * s, sc = s * c;
    u64 M00 = ffma2(bc2(ss), W01, ffma2(bc2(-sc), S0, fmul2(bc2(cc), W00)));
    u64 M01 = ffma2(bc2(-ss), W00, ffma2(bc2(sc), D0, fmul2(bc2(cc), W01)));
    up2(M00, m00r, m00i); up2(M01, m01r, m01i);
}

// Fused pass with software-pipelined shuffles: pack k+1's 4 SHFLs are issued
// before pack k's FMAs consume the previously prefetched values, hiding the
// SHFL latency under FMA work. Lane gate and second gate act on distinct
// qubits (commute); second-gate writes only touch indices <= k, never k+1,
// and all lanes reach each shfl at the same program point, so prefetched
// partner values are consistently pre-gate.
// TK > 0: second gate is the k-bit gate with target bit TK.
// TK == 0: second gate is the slot gate (within-pack).
template <int TK>
__device__ __forceinline__ void fused_pass(
    u64* pr, u64* pi, int msk,
    u64 AAr, u64 AAi, u64 AAin, u64 ABr, u64 ABi, u64 ABin,
    u64 G0, u64 G1, u64 G2, u64 G3, u64 G4, u64 G5, u64 G6)
{
    float c0, c1, c2, c3;
    {
        float a0, a1, b0, b1;
        up2(pr[0], a0, a1); up2(pi[0], b0, b1);
        c0 = __shfl_xor_sync(FULL, a0, msk);
        c1 = __shfl_xor_sync(FULL, a1, msk);
        c2 = __shfl_xor_sync(FULL, b0, msk);
        c3 = __shfl_xor_sync(FULL, b1, msk);
    }
#pragma unroll
    for (int k = 0; k < 16; k++) {
        float n0, n1, n2, n3;
        if (k < 15) {
            float a0, a1, b0, b1;
            up2(pr[k + 1], a0, a1); up2(pi[k + 1], b0, b1);
            n0 = __shfl_xor_sync(FULL, a0, msk);
            n1 = __shfl_xor_sync(FULL, a1, msk);
            n2 = __shfl_xor_sync(FULL, b0, msk);
            n3 = __shfl_xor_sync(FULL, b1, msk);
        }
        // --- lane-bit gate on pack k (uses prefetched partner values) ---
        {
            u64 OTR = pk2(c0, c1), OTI = pk2(c2, c3);
            u64 AR = pr[k], AI = pi[k];
            pr[k] = ffma2(ABin, OTI, ffma2(ABr, OTR, ffma2(AAin, AI, fmul2(AAr, AR))));
            pi[k] = ffma2(ABi, OTR, ffma2(ABr, OTI, ffma2(AAi, AR, fmul2(AAr, AI))));
        }
        // --- second gate (independent qubit, pure FMA) ---
        if (TK > 0) {
            // k-bit gate: G0..G6 = P00r,P00i,P00in,P01r,P01i,P01in,P01rn
            if (k & TK) {
                const int k0 = k ^ TK;
                u64 p0r = pr[k0], p0i = pi[k0], p1r = pr[k], p1i = pi[k];
                pr[k0] = ffma2(G5, p1i, ffma2(G3, p1r, ffma2(G2, p0i, fmul2(G0, p0r))));
                pi[k0] = ffma2(G4, p1r, ffma2(G3, p1i, ffma2(G1, p0r, fmul2(G0, p0i))));
                pr[k]  = ffma2(G1, p1i, ffma2(G0, p1r, ffma2(G5, p0i, fmul2(G6, p0r))));
                pi[k]  = ffma2(G2, p1r, ffma2(G0, p1i, ffma2(G4, p0r, fmul2(G6, p0i))));
            }
        } else {
            // slot gate: G0..G5 = C1,C2,C3,C4,E1,E4
            u64 P = pr[k], Q = pi[k];
            u64 SP = swap2(P), SQ = swap2(Q);
            pr[k] = ffma2(G3, SQ, ffma2(G2, SP, ffma2(G1, Q, fmul2(G0, P))));
            pi[k] = ffma2(G5, SP, ffma2(G2, SQ, ffma2(G4, P, fmul2(G0, Q))));
        }
        c0 = n0; c1 = n1; c2 = n2; c3 = n3;
    }
}

__global__ void __launch_bounds__(128, 4) qsim_kernel(
    const float* __restrict__ x,
    const float* __restrict__ in_W,
    const float* __restrict__ in_b,
    const float* __restrict__ gamma,
    const float* __restrict__ beta,
    const float* __restrict__ out_b,
    float* __restrict__ out)
{
    const int tid  = threadIdx.x;
    const int lane = tid & 31;
    const int warp = tid >> 5;
    const int token = blockIdx.x * 4 + warp;
    const float* xrow = x + (size_t)token * DM;

    __shared__ float s_cx[NQ][128], s_sx[NQ][128];

    // ---------------- Stage 1: h = tanh(x @ in_W^T + b), LayerNorm ----------
    float acc[NQ];
    {
        ulonglong2 xv[4];
#pragma unroll
        for (int i = 0; i < 4; i++)
            xv[i] = *(const ulonglong2*)(xrow + lane * 4 + 128 * i);
#pragma unroll
        for (int q = 0; q < NQ; q++) {
            u64 a2 = 0;
#pragma unroll
            for (int i = 0; i < 4; i++) {
                ulonglong2 w = *(const ulonglong2*)(in_W + q * DM + lane * 4 + 128 * i);
                a2 = ffma2(xv[i].x, w.x, a2);
                a2 = ffma2(xv[i].y, w.y, a2);
            }
            float s0, s1; up2(a2, s0, s1);
            acc[q] = warp_sum(s0 + s1);
        }
    }
    float mu = 0.f;
#pragma unroll
    for (int q = 0; q < NQ; q++) {
        float t = acc[q] + __ldg(&in_b[q]);
        float e = __expf(2.f * t);
        acc[q] = 1.f - __fdividef(2.f, e + 1.f);   // tanh
        mu += acc[q];
    }
    mu *= 0.1f;
    float var = 0.f;
#pragma unroll
    for (int q = 0; q < NQ; q++) { float d = acc[q] - mu; var = fmaf(d, d, var); }
    var *= 0.1f;
    float rstd = rsqrtf(var + 1e-5f);
#pragma unroll
    for (int q = 0; q < NQ; q++) {
        float feat = fmaf((acc[q] - mu) * rstd, __ldg(&gamma[q]), __ldg(&beta[q]));
        float sn, cs;
        __sincosf(0.5f * feat, &sn, &cs);
        s_cx[q][tid] = cs; s_sx[q][tid] = sn;
    }

    // ---------------- Stage 2: 10-qubit statevector sim ---------------------
    // amp index = (vlane << 5) | r, r = 2k + slot, qubit q <-> amp bit (9-q)
    // pr[k]/pi[k] pack amps (r=2k, r=2k+1) re/im as f32x2.
    u64 pr[16], pi[16];

    // --- Layer 0: |0..0> is a product state; build by progressive doubling.
    {
        float m00r, m00i, m01r, m01i;
        // slot level (qubit 9); column0 = (m00, m10) = (m00, -conj(m01))
        build_m2(0, 9, s_cx[9][tid], s_sx[9][tid], m00r, m00i, m01r, m01i);
        pr[0] = pk2(m00r, -m01r);
        pi[0] = pk2(m00i,  m01i);
#pragma unroll
        for (int b = 1; b <= 4; b++) {
            const int qb = 9 - b;
            build_m2(0, qb, s_cx[qb][tid], s_sx[qb][tid], m00r, m00i, m01r, m01i);
            u64 C0r = bc2(m00r), C0i = bc2(m00i), C0in = bc2(-m00i);
            u64 C1r = bc2(-m01r), C1i = bc2(m01i), C1in = bc2(-m01i);
            const int half = 1 << (b - 1);
#pragma unroll
            for (int k = 0; k < 8; k++) {
                if (k >= half) continue;
                u64 fr = pr[k], fi = pi[k];
                pr[k + half] = ffma2(C1in, fi, fmul2(C1r, fr));
                pi[k + half] = ffma2(C1i, fr, fmul2(C1r, fi));
                pr[k] = ffma2(C0in, fi, fmul2(C0r, fr));
                pi[k] = ffma2(C0i, fr, fmul2(C0r, fi));
            }
        }
        // lane factor over qubits 0..4 (lane bit 4-q)
        float lfr = 1.f, lfi = 0.f;
#pragma unroll
        for (int q = 0; q < 5; q++) {
            build_m2(0, q, s_cx[q][tid], s_sx[q][tid], m00r, m00i, m01r, m01i);
            int v = (lane >> (4 - q)) & 1;
            float gr = v ? -m01r : m00r, gi = v ? m01i : m00i;
            float nr = lfr * gr - lfi * gi;
            float ni = lfr * gi + lfi * gr;
            lfr = nr; lfi = ni;
        }
        u64 LFr = bc2(lfr), LFi = bc2(lfi), LFin = bc2(-lfi);
#pragma unroll
        for (int k = 0; k < 16; k++) {
            u64 fr = pr[k], fi = pi[k];
            pr[k] = ffma2(LFin, fi, fmul2(LFr, fr));
            pi[k] = ffma2(LFi, fr, fmul2(LFr, fi));
        }
    }

    // relabel state: vlane = sigma^{-L}(lane); m0..m4 = sigma^L(1<<b)
    int vlane = lane;
    int m0 = 1, m1 = 2, m2 = 4, m3 = 8, m4 = 16;

#pragma unroll 1
    for (int l = 0; l < QL; l++) {
        if (l) {
            float m00r, m00i, m01r, m01i;
            float k00r, k00i, k01r, k01i;
            // 5 fused passes: (lane q0,k q5), (q1,q6), (q2,q7), (q3,q8), (q4,slot q9)
#define LANE_COEFFS(Q, MSKEXPR)                                                \
            build_m2(l, (Q), s_cx[(Q)][tid], s_sx[(Q)][tid],                   \
                     m00r, m00i, m01r, m01i);                                  \
            const int msk_##Q = (MSKEXPR);                                     \
            const int v_##Q = (vlane >> (4 - (Q))) & 1;                        \
            const float aai_##Q = v_##Q ? -m00i : m00i;                        \
            const float abr_##Q = v_##Q ? -m01r : m01r;                        \
            u64 AAr = bc2(m00r), AAi = bc2(aai_##Q), AAin = bc2(-aai_##Q);     \
            u64 ABr = bc2(abr_##Q), ABi = bc2(m01i), ABin = bc2(-m01i);

            { // pass 0: lane q0 (msk m4) + k-gate q5 (tk=8)
                LANE_COEFFS(0, m4)
                build_m2(l, 5, s_cx[5][tid], s_sx[5][tid], k00r, k00i, k01r, k01i);
                fused_pass<8>(pr, pi, msk_0, AAr, AAi, AAin, ABr, ABi, ABin,
                    bc2(k00r), bc2(k00i), bc2(-k00i),
                    bc2(k01r), bc2(k01i), bc2(-k01i), bc2(-k01r));
            }
            { // pass 1: lane q1 (msk m3) + k-gate q6 (tk=4)
                LANE_COEFFS(1, m3)
                build_m2(l, 6, s_cx[6][tid], s_sx[6][tid], k00r, k00i, k01r, k01i);
                fused_pass<4>(pr, pi, msk_1, AAr, AAi, AAin, ABr, ABi, ABin,
                    bc2(k00r), bc2(k00i), bc2(-k00i),
                    bc2(k01r), bc2(k01i), bc2(-k01i), bc2(-k01r));
            }
            { // pass 2: lane q2 (msk m2) + k-gate q7 (tk=2)
                LANE_COEFFS(2, m2)
                build_m2(l, 7, s_cx[7][tid], s_sx[7][tid], k00r, k00i, k01r, k01i);
                fused_pass<2>(pr, pi, msk_2, AAr, AAi, AAin, ABr, ABi, ABin,
                    bc2(k00r), bc2(k00i), bc2(-k00i),
                    bc2(k01r), bc2(k01i), bc2(-k01i), bc2(-k01r));
            }
            { // pass 3: lane q3 (msk m1) + k-gate q8 (tk=1)
                LANE_COEFFS(3, m1)
                build_m2(l, 8, s_cx[8][tid], s_sx[8][tid], k00r, k00i, k01r, k01i);
                fused_pass<1>(pr, pi, msk_3, AAr, AAi, AAin, ABr, ABi, ABin,
                    bc2(k00r), bc2(k00i), bc2(-k00i),
                    bc2(k01r), bc2(k01i), bc2(-k01i), bc2(-k01r));
            }
            { // pass 4: lane q4 (msk m0) + slot gate q9
                LANE_COEFFS(4, m0)
                build_m2(l, 9, s_cx[9][tid], s_sx[9][tid], k00r, k00i, k01r, k01i);
                // C1,C2,C3,C4,E1,E4
                fused_pass<0>(pr, pi, msk_4, AAr, AAi, AAin, ABr, ABi, ABin,
                    bc2(k00r), pk2(-k00i, k00i), pk2(k01r, -k01r),
                    bc2(-k01i), pk2(k00i, -k00i), bc2(k01i), 0);
            }
#undef LANE_COEFFS
        }

        // ---------------- CNOT chain (layers 0..2; layer 3 absorbed) --------
        if (l < 3) {
            // q=0..3 lane perm: SKIPPED -> advance the GF(2) relabeling
            vlane = vlane ^ (vlane >> 1) ^ (vlane >> 2) ^ (vlane >> 3) ^ (vlane >> 4);
            m0 ^= m0 >> 1; m1 ^= m1 >> 1; m2 ^= m2 >> 1; m3 ^= m3 >> 1; m4 ^= m4 >> 1;
            // q=4: control virtual lane bit0, target k bit3
            {
                const bool flip = (vlane & 1);
#pragma unroll
                for (int k = 0; k < 8; k++) {
                    u64 t = pr[k]; pr[k] = flip ? pr[k + 8] : t; pr[k + 8] = flip ? t : pr[k + 8];
                    u64 u = pi[k]; pi[k] = flip ? pi[k + 8] : u; pi[k + 8] = flip ? u : pi[k + 8];
                }
            }
            // q=5..7: pure register swaps (free renames)
#pragma unroll
            for (int q = 5; q < 8; q++) {
                const int ck = 1 << (8 - q), tk2 = 1 << (7 - q);
#pragma unroll
                for (int k = 0; k < 16; k++) {
                    if ((k & ck) && !(k & tk2)) {
                        const int k2 = k | tk2;
                        u64 t = pr[k]; pr[k] = pr[k2]; pr[k2] = t;
                        u64 u = pi[k]; pi[k] = pi[k2]; pi[k2] = u;
                    }
                }
            }
            // q=8: control k bit0, target slot -> swap pack halves for odd k
#pragma unroll
            for (int k = 1; k < 16; k += 2) { pr[k] = swap2(pr[k]); pi[k] = swap2(pi[k]); }
            // q=9: control slot, target virtual lane bit4 -> shuffle hi halves across m4
#pragma unroll
            for (int k = 0; k < 16; k++) {
                float a, b;
                up2(pr[k], a, b); b = __shfl_xor_sync(FULL, b, m4); pr[k] = pk2(a, b);
                up2(pi[k], a, b); b = __shfl_xor_sync(FULL, b, m4); pi[k] = pk2(a, b);
            }
        }
    }

    // ---------------- Stage 3: measurement (final CNOT chain absorbed) ------
    // Final chain is GF(2)-linear on the amp index: post bit B'(q)=9-q maps to
    //   B'=0..8: parity(orig bits B'..9);  B'=9: parity(orig bits 0..8).
    // orig bits: slot = bit0, k = bits1..4, vlane = bits5..9 (virtual!).
    const u64 SGN = 0x8000000080000000ULL;
    u64 AT = 0, A1 = 0, A2 = 0, A3 = 0, A4 = 0;
#pragma unroll
    for (int k = 0; k < 16; k++) {
        u64 P = ffma2(pi[k], pi[k], fmul2(pr[k], pr[k]));
        u64 NP = P ^ SGN;
        const int k3 = (k >> 3) & 1, k2b = (k >> 2) & 1, k1 = (k >> 1) & 1, k0 = k & 1;
        AT = fadd2(AT, P);
        A1 = fadd2(A1, k3 ? NP : P);
        A2 = fadd2(A2, (k3 ^ k2b) ? NP : P);
        A3 = fadd2(A3, (k3 ^ k2b ^ k1) ? NP : P);
        A4 = fadd2(A4, (k3 ^ k2b ^ k1 ^ k0) ? NP : P);
    }
    float lo, hi;
    up2(AT, lo, hi); const float T  = lo + hi;
    up2(A1, lo, hi); const float U1 = lo + hi;
    up2(A2, lo, hi); const float U2 = lo + hi;
    up2(A3, lo, hi); const float U3 = lo + hi;
    up2(A4, lo, hi); const float U4 = lo + hi, Dp = lo - hi;

    const int pl  = __popc(vlane) & 1;
    const int pl4 = __popc(vlane & 15) & 1;
    float z[NQ];
    z[0] = warp_sum(pl4 ? -Dp : Dp);
    z[1] = warp_sum((__popc(vlane >> 3) & 1) ? -T : T);
    z[2] = warp_sum((__popc(vlane >> 2) & 1) ? -T : T);
    z[3] = warp_sum((__popc(vlane >> 1) & 1) ? -T : T);
    z[4] = warp_sum(pl ? -T : T);
    z[5] = warp_sum(pl ? -U1 : U1);
    z[6] = warp_sum(pl ? -U2 : U2);
    z[7] = warp_sum(pl ? -U3 : U3);
    z[8] = warp_sum(pl ? -U4 : U4);
    z[9] = warp_sum(pl ? -Dp : Dp);

    // out = x + q_out @ out_W^T + out_b  (via transposed g_WT, f32x2 lanes)
    u64 zb[NQ];
#pragma unroll
    for (int q = 0; q < NQ; q++) zb[q] = bc2(z[q]);

    float* outr = out + (size_t)token * DM;
#pragma unroll
    for (int i = 0; i < 4; i++) {
        const int dbase = lane * 4 + 128 * i;
        const int j = dbase >> 1;
        u64 a0 = 0, a1 = 0;
#pragma unroll
        for (int q = 0; q < NQ; q++) {
            ulonglong2 w = *(const ulonglong2*)(&g_WT[q][j]);
            a0 = ffma2(zb[q], w.x, a0);
            a1 = ffma2(zb[q], w.y, a1);
        }
        float4 xv = *(const float4*)(xrow + dbase);
        float4 ob = *(const float4*)(out_b + dbase);
        float r0, r1, r2, r3;
        up2(a0, r0, r1); up2(a1, r2, r3);
        float4 o;
        o.x = xv.x + ob.x + r0;
        o.y = xv.y + ob.y + r1;
        o.z = xv.z + ob.z + r2;
        o.w = xv.w + ob.w + r3;
        *(float4*)(outr + dbase) = o;
    }
}

extern "C" void kernel_launch(void* const* d_in, const int* in_sizes, int n_in,
                              void* d_out, int out_size) {
    const float* x       = (const float*)d_in[0];
    const float* in_W    = (const float*)d_in[1];
    const float* in_b    = (const float*)d_in[2];
    const float* gamma   = (const float*)d_in[3];
    const float* beta    = (const float*)d_in[4];
    const float* weights = (const float*)d_in[5];
    const float* out_W   = (const float*)d_in[6];
    const float* out_b   = (const float*)d_in[7];
    float* out = (float*)d_out;

    prep_kernel<<<1, 256>>>(weights, out_W);
    qsim_kernel<<<NTOK / 4, 128>>>(x, in_W, in_b, gamma, beta, out_b, out);
}